// round 4
// baseline (speedup 1.0000x reference)
#include <cuda_runtime.h>
#include <math.h>

#define DD 128

static const int MAXP = 200000;
static const int MAXA = 30000;
static const int MAXS = 50000;
static const int MAXSRC = 50000;      // max rows ever pre-transformed (song)
static const int MAXE_TOT = 2000000;
static const int MAXN_TOT = 560000 + 64;

// ---------------- scratch (static __device__, no allocations) ----------------
__device__ float g_xp[MAXP * DD];
__device__ float g_xa[MAXA * DD];
__device__ float g_xs[MAXS * DD];
__device__ float g_yp[MAXP * DD];
__device__ float g_ya[MAXA * DD];
__device__ float g_ys[MAXS * DD];
__device__ float g_agg[MAXP * DD];
__device__ float g_tmp[MAXSRC * DD];
__device__ int g_rowptr[MAXN_TOT];
__device__ int g_cnt[MAXN_TOT];
__device__ int g_cursor[MAXN_TOT];
__device__ int g_srcs[MAXE_TOT];
__device__ int g_part[1024];

// ---------------- small helpers ----------------
__device__ __forceinline__ float4 ld4(const float* p) { return *reinterpret_cast<const float4*>(p); }
__device__ __forceinline__ void st4(float* p, float4 v) { *reinterpret_cast<float4*>(p) = v; }
__device__ __forceinline__ float4 f4add(float4 a, float4 b) {
    return make_float4(a.x + b.x, a.y + b.y, a.z + b.z, a.w + b.w);
}
__device__ __forceinline__ float4 f4fma(float4 acc, float s, float4 w) {
    acc.x = fmaf(s, w.x, acc.x);
    acc.y = fmaf(s, w.y, acc.y);
    acc.z = fmaf(s, w.z, acc.z);
    acc.w = fmaf(s, w.w, acc.w);
    return acc;
}

// ---------------- utility kernels ----------------
__global__ void k_zero(int* p, int n) {
    int i = blockIdx.x * blockDim.x + threadIdx.x;
    if (i < n) p[i] = 0;
}

// x[r] = emb[nid[r]]  (float4 granularity)
__global__ void k_gather(const float* __restrict__ emb, const int* __restrict__ nid,
                         float* __restrict__ x, int n) {
    int i = blockIdx.x * blockDim.x + threadIdx.x;
    if (i < n * 32) {
        int r = i >> 5, c = i & 31;
        st4(x + (size_t)r * DD + c * 4, ld4(emb + (size_t)nid[r] * DD + c * 4));
    }
}

__global__ void k_count(const int* __restrict__ dst, int E, int* cnt) {
    int e = blockIdx.x * blockDim.x + threadIdx.x;
    if (e < E) atomicAdd(&cnt[dst[e]], 1);
}

__global__ void k_scan1(const int* __restrict__ cnt, int* __restrict__ rowptr,
                        int* __restrict__ part, int N) {
    __shared__ int s[512];
    int tid = threadIdx.x;
    int i = blockIdx.x * 512 + tid;
    int v = (i < N) ? cnt[i] : 0;
    s[tid] = v;
    __syncthreads();
    for (int off = 1; off < 512; off <<= 1) {
        int t = (tid >= off) ? s[tid - off] : 0;
        __syncthreads();
        s[tid] += t;
        __syncthreads();
    }
    if (i < N) rowptr[i] = s[tid] - v;  // exclusive
    if (tid == 511) part[blockIdx.x] = s[511];
}

__global__ void k_scan2(int* part, int n) {
    __shared__ int s[512];
    int tid = threadIdx.x;
    int v = (tid < n) ? part[tid] : 0;
    s[tid] = v;
    __syncthreads();
    for (int off = 1; off < 512; off <<= 1) {
        int t = (tid >= off) ? s[tid - off] : 0;
        __syncthreads();
        s[tid] += t;
        __syncthreads();
    }
    if (tid < n) part[tid] = s[tid] - v;  // exclusive
}

__global__ void k_scan3(int* rowptr, const int* __restrict__ part, int N) {
    int i = blockIdx.x * blockDim.x + threadIdx.x;
    if (i < N) rowptr[i] += part[i >> 9];
}

__global__ void k_scatter(const int* __restrict__ src, const int* __restrict__ dst, int E,
                          const int* __restrict__ rowptr, int* __restrict__ cursor,
                          int* __restrict__ out) {
    int e = blockIdx.x * blockDim.x + threadIdx.x;
    if (e < E) {
        int d = dst[e];
        int pos = rowptr[d] + atomicAdd(&cursor[d], 1);
        out[pos] = src[e];
    }
}

// segment-mean gather: one warp per destination row
__global__ void k_agg(const float* __restrict__ feat, const int* __restrict__ rowptr,
                      const int* __restrict__ cnt, const int* __restrict__ srcs,
                      float* __restrict__ out, int N) {
    int warp = (blockIdx.x * blockDim.x + threadIdx.x) >> 5;
    if (warp >= N) return;
    int lane = threadIdx.x & 31;
    int beg = rowptr[warp], n = cnt[warp];
    float4 acc = make_float4(0.f, 0.f, 0.f, 0.f);
    int i = 0;
    for (; i + 4 <= n; i += 4) {
        int s0 = srcs[beg + i], s1 = srcs[beg + i + 1];
        int s2 = srcs[beg + i + 2], s3 = srcs[beg + i + 3];
        float4 v0 = ld4(feat + (size_t)s0 * DD + lane * 4);
        float4 v1 = ld4(feat + (size_t)s1 * DD + lane * 4);
        float4 v2 = ld4(feat + (size_t)s2 * DD + lane * 4);
        float4 v3 = ld4(feat + (size_t)s3 * DD + lane * 4);
        acc = f4add(acc, f4add(f4add(v0, v1), f4add(v2, v3)));
    }
    for (; i < n; i++) {
        int s = srcs[beg + i];
        acc = f4add(acc, ld4(feat + (size_t)s * DD + lane * 4));
    }
    float inv = 1.0f / (float)max(n, 1);
    acc.x *= inv; acc.y *= inv; acc.z *= inv; acc.w *= inv;
    st4(out + (size_t)warp * DD + lane * 4, acc);
}

// layernorm: one warp per row
__global__ void k_ln(const float* __restrict__ x, const float* __restrict__ g,
                     const float* __restrict__ b, float* __restrict__ y, int N) {
    int warp = (blockIdx.x * blockDim.x + threadIdx.x) >> 5;
    if (warp >= N) return;
    int lane = threadIdx.x & 31;
    float4 v = ld4(x + (size_t)warp * DD + lane * 4);
    float s = v.x + v.y + v.z + v.w;
#pragma unroll
    for (int m = 16; m > 0; m >>= 1) s += __shfl_xor_sync(0xffffffffu, s, m);
    float mu = s * (1.0f / 128.0f);
    float4 d = make_float4(v.x - mu, v.y - mu, v.z - mu, v.w - mu);
    float ss = d.x * d.x + d.y * d.y + d.z * d.z + d.w * d.w;
#pragma unroll
    for (int m = 16; m > 0; m >>= 1) ss += __shfl_xor_sync(0xffffffffu, ss, m);
    float sc = rsqrtf(ss * (1.0f / 128.0f) + 1e-5f);
    float4 gv = ld4(g + lane * 4), bv = ld4(b + lane * 4);
    float4 o = make_float4(d.x * sc * gv.x + bv.x, d.y * sc * gv.y + bv.y,
                           d.z * sc * gv.z + bv.z, d.w * sc * gv.w + bv.w);
    st4(y + (size_t)warp * DD + lane * 4, o);
}

// ---------------- fused GEMM ----------------
// h = (U1 ? A1@W1 : 0) + (U2 ? A2@W2 : 0) + (HASPASS ? pass : 0) + (HASB ? bias : 0)
// EPI: 0 = store; 1 = l2norm store; 2 = l2norm add; 3 = l2norm add + relu; 4 = relu store
// Tile: 64 rows x 128 cols, 256 threads, warp w -> rows 8w..8w+7, lane -> cols 4*lane..
template <bool U1, bool U2, bool HASB, bool HASPASS, int EPI>
__global__ void __launch_bounds__(256, 2)
k_gemm(const float* __restrict__ A1, const float* __restrict__ W1,
       const float* __restrict__ A2, const float* __restrict__ W2,
       const float* __restrict__ bias, const float* __restrict__ pass,
       float* __restrict__ out, int N) {
    constexpr int SA = 64 * 32;
    constexpr int SW = 32 * 128;
    constexpr int S1 = (U1 ? SA + SW : 0);
    constexpr int S2 = (U2 ? SA + SW : 0);
    static_assert((S1 + S2) * 4 <= 49152, "static smem over limit");
    __shared__ float sb[S1 + S2];
    float* sA1 = sb;
    float* sW1 = sb + SA;
    float* sA2 = sb + S1;
    float* sW2 = sb + S1 + SA;

    int row0 = blockIdx.x * 64;
    int tid = threadIdx.x;
    int warp = tid >> 5, lane = tid & 31;

    float4 acc[8];
#pragma unroll
    for (int r = 0; r < 8; r++) acc[r] = make_float4(0.f, 0.f, 0.f, 0.f);

    for (int k0 = 0; k0 < 128; k0 += 32) {
        __syncthreads();
        // activation tiles: 64x32 floats = 512 float4 -> 2 per thread
#pragma unroll
        for (int i = 0; i < 2; i++) {
            int idx = tid + i * 256;
            int r = idx >> 3, c = idx & 7;
            int grow = row0 + r;
            float4 z = make_float4(0.f, 0.f, 0.f, 0.f);
            if constexpr (U1) {
                float4 v = (grow < N) ? ld4(A1 + (size_t)grow * 128 + k0 + c * 4) : z;
                st4(sA1 + r * 32 + c * 4, v);
            }
            if constexpr (U2) {
                float4 v = (grow < N) ? ld4(A2 + (size_t)grow * 128 + k0 + c * 4) : z;
                st4(sA2 + r * 32 + c * 4, v);
            }
        }
        // weight tiles: 32x128 floats = 1024 float4 -> 4 per thread
#pragma unroll
        for (int i = 0; i < 4; i++) {
            int idx = tid + i * 256;
            int r = idx >> 5, c = idx & 31;
            if constexpr (U1) st4(sW1 + r * 128 + c * 4, ld4(W1 + (size_t)(k0 + r) * 128 + c * 4));
            if constexpr (U2) st4(sW2 + r * 128 + c * 4, ld4(W2 + (size_t)(k0 + r) * 128 + c * 4));
        }
        __syncthreads();

#pragma unroll
        for (int kk = 0; kk < 32; kk += 4) {
            float4 w1[4], w2[4];
            if constexpr (U1) {
#pragma unroll
                for (int j = 0; j < 4; j++) w1[j] = ld4(sW1 + (kk + j) * 128 + lane * 4);
            }
            if constexpr (U2) {
#pragma unroll
                for (int j = 0; j < 4; j++) w2[j] = ld4(sW2 + (kk + j) * 128 + lane * 4);
            }
#pragma unroll
            for (int r = 0; r < 8; r++) {
                if constexpr (U1) {
                    float4 a = ld4(sA1 + (warp * 8 + r) * 32 + kk);
                    acc[r] = f4fma(acc[r], a.x, w1[0]);
                    acc[r] = f4fma(acc[r], a.y, w1[1]);
                    acc[r] = f4fma(acc[r], a.z, w1[2]);
                    acc[r] = f4fma(acc[r], a.w, w1[3]);
                }
                if constexpr (U2) {
                    float4 a = ld4(sA2 + (warp * 8 + r) * 32 + kk);
                    acc[r] = f4fma(acc[r], a.x, w2[0]);
                    acc[r] = f4fma(acc[r], a.y, w2[1]);
                    acc[r] = f4fma(acc[r], a.z, w2[2]);
                    acc[r] = f4fma(acc[r], a.w, w2[3]);
                }
            }
        }
    }

    // epilogue
    float4 bv = make_float4(0.f, 0.f, 0.f, 0.f);
    if constexpr (HASB) bv = ld4(bias + lane * 4);
#pragma unroll
    for (int r = 0; r < 8; r++) {
        int grow = row0 + warp * 8 + r;
        if (grow >= N) continue;  // uniform per warp
        float4 h = acc[r];
        if constexpr (HASPASS) h = f4add(h, ld4(pass + (size_t)grow * 128 + lane * 4));
        if constexpr (HASB) h = f4add(h, bv);
        float* op = out + (size_t)grow * 128 + lane * 4;
        if constexpr (EPI == 0) {
            st4(op, h);
        } else if constexpr (EPI == 4) {
            h.x = fmaxf(h.x, 0.f); h.y = fmaxf(h.y, 0.f);
            h.z = fmaxf(h.z, 0.f); h.w = fmaxf(h.w, 0.f);
            st4(op, h);
        } else {
            float ssq = h.x * h.x + h.y * h.y + h.z * h.z + h.w * h.w;
#pragma unroll
            for (int m = 16; m > 0; m >>= 1) ssq += __shfl_xor_sync(0xffffffffu, ssq, m);
            float sc = 1.0f / fmaxf(sqrtf(ssq), 1e-12f);
            h.x *= sc; h.y *= sc; h.z *= sc; h.w *= sc;
            if constexpr (EPI == 1) {
                st4(op, h);
            } else {
                float4 prev = ld4(op);
                h = f4add(h, prev);
                if constexpr (EPI == 3) {
                    h.x = fmaxf(h.x, 0.f); h.y = fmaxf(h.y, 0.f);
                    h.z = fmaxf(h.z, 0.f); h.w = fmaxf(h.w, 0.f);
                }
                st4(op, h);
            }
        }
    }
}

// ---------------- host orchestration ----------------
extern "C" void kernel_launch(void* const* d_in, const int* in_sizes, int n_in,
                              void* d_out, int out_size) {
    const int* nidP = (const int*)d_in[0];
    const int* nidA = (const int*)d_in[1];
    const int* nidS = (const int*)d_in[2];
    const int* Eptr[6];
    int Ecnt[6];
    for (int r = 0; r < 6; r++) {
        Eptr[r] = (const int*)d_in[3 + r];
        Ecnt[r] = in_sizes[3 + r] / 2;
    }
    const float* embP = (const float*)d_in[9];
    const float* embA = (const float*)d_in[10];
    const float* embS = (const float*)d_in[11];
    const float* Wl = (const float*)d_in[12];
    const float* bl = (const float*)d_in[13];
    const float* Wr = (const float*)d_in[14];
    const float* lng = (const float*)d_in[15];
    const float* lnb = (const float*)d_in[16];
    const float* pw1 = (const float*)d_in[17];
    const float* pb1 = (const float*)d_in[18];
    const float* pw2 = (const float*)d_in[19];
    const float* pb2 = (const float*)d_in[20];
    int NPn = in_sizes[0], NAn = in_sizes[1], NSn = in_sizes[2];

    float *xp, *xa, *xs, *yp, *ya, *ys, *agg, *tmp;
    int *rowptr, *cnt, *cursor, *srcs, *part;
    cudaGetSymbolAddress((void**)&xp, g_xp);
    cudaGetSymbolAddress((void**)&xa, g_xa);
    cudaGetSymbolAddress((void**)&xs, g_xs);
    cudaGetSymbolAddress((void**)&yp, g_yp);
    cudaGetSymbolAddress((void**)&ya, g_ya);
    cudaGetSymbolAddress((void**)&ys, g_ys);
    cudaGetSymbolAddress((void**)&agg, g_agg);
    cudaGetSymbolAddress((void**)&tmp, g_tmp);
    cudaGetSymbolAddress((void**)&rowptr, g_rowptr);
    cudaGetSymbolAddress((void**)&cnt, g_cnt);
    cudaGetSymbolAddress((void**)&cursor, g_cursor);
    cudaGetSymbolAddress((void**)&srcs, g_srcs);
    cudaGetSymbolAddress((void**)&part, g_part);

    // relation meta: dst/src type per relation; type ids: 0=perf,1=artist,2=song
    int Ndst[6] = {NPn, NSn, NSn, NAn, NPn, NAn};
    int dstT[6] = {0, 2, 2, 1, 0, 1};
    int srcT[6] = {1, 0, 1, 0, 2, 2};
    bool pre[6] = {true, false, true, false, true, false};  // transform at source?
    int roff[6], eoff[6];
    {
        int o = 0;
        for (int r = 0; r < 6; r++) { roff[r] = o; o += Ndst[r]; }
        o = 0;
        for (int r = 0; r < 6; r++) { eoff[r] = o; o += Ecnt[r]; }
    }

    // init features from embeddings
    k_gather<<<(NPn * 32 + 255) / 256, 256>>>(embP, nidP, xp, NPn);
    k_gather<<<(NAn * 32 + 255) / 256, 256>>>(embA, nidA, xa, NAn);
    k_gather<<<(NSn * 32 + 255) / 256, 256>>>(embS, nidS, xs, NSn);

    // build CSR per relation (edges are layer-invariant)
    for (int r = 0; r < 6; r++) {
        int Nd = Ndst[r], E = Ecnt[r];
        const int* srcp = Eptr[r];
        const int* dstp = Eptr[r] + E;
        int nb = (Nd + 511) / 512;
        k_zero<<<(Nd + 255) / 256, 256>>>(cnt + roff[r], Nd);
        k_zero<<<(Nd + 255) / 256, 256>>>(cursor + roff[r], Nd);
        k_count<<<(E + 255) / 256, 256>>>(dstp, E, cnt + roff[r]);
        k_scan1<<<nb, 512>>>(cnt + roff[r], rowptr + roff[r], part, Nd);
        k_scan2<<<1, 512>>>(part, nb);
        k_scan3<<<(Nd + 255) / 256, 256>>>(rowptr + roff[r], part, Nd);
        k_scatter<<<(E + 255) / 256, 256>>>(srcp, dstp, E, rowptr + roff[r], cursor + roff[r],
                                            srcs + eoff[r]);
    }

    float* X[3] = {xp, xa, xs};
    float* Y[3] = {yp, ya, ys};
    int Nt[3] = {NPn, NAn, NSn};
    int Ns_of[3] = {NPn, NAn, NSn};

    // process relations grouped by destination type: (first, second) per type
    int order[6] = {0, 4, 1, 2, 3, 5};

    for (int layer = 0; layer < 3; layer++) {
        bool relu = (layer < 2);
        for (int oi = 0; oi < 6; oi++) {
            int r = order[oi];
            bool isFirst = (oi % 2 == 0);
            int Nd = Ndst[r];
            int st = srcT[r], dt = dstT[r];
            int Ns = Ns_of[st];
            const float* Wlr = Wl + ((size_t)layer * 6 + r) * 16384;
            const float* Wrr = Wr + ((size_t)layer * 6 + r) * 16384;
            const float* blr = bl + ((size_t)layer * 6 + r) * 128;
            int gb = (Nd + 63) / 64;
            int ab = (Nd * 32 + 255) / 256;
            if (pre[r]) {
                // tmp = X[src] @ Wl  (src side is artist or song: <= 50k rows)
                k_gemm<true, false, false, false, 0><<<(Ns + 63) / 64, 256>>>(
                    X[st], Wlr, nullptr, nullptr, nullptr, nullptr, tmp, Ns);
                k_agg<<<ab, 256>>>(tmp, rowptr + roff[r], cnt + roff[r], srcs + eoff[r], agg, Nd);
                if (isFirst)
                    k_gemm<false, true, true, true, 1><<<gb, 256>>>(
                        nullptr, nullptr, X[dt], Wrr, blr, agg, Y[dt], Nd);
                else if (relu)
                    k_gemm<false, true, true, true, 3><<<gb, 256>>>(
                        nullptr, nullptr, X[dt], Wrr, blr, agg, Y[dt], Nd);
                else
                    k_gemm<false, true, true, true, 2><<<gb, 256>>>(
                        nullptr, nullptr, X[dt], Wrr, blr, agg, Y[dt], Nd);
            } else {
                k_agg<<<ab, 256>>>(X[st], rowptr + roff[r], cnt + roff[r], srcs + eoff[r], agg, Nd);
                if (isFirst)
                    k_gemm<true, true, true, false, 1><<<gb, 256>>>(
                        agg, Wlr, X[dt], Wrr, blr, nullptr, Y[dt], Nd);
                else if (relu)
                    k_gemm<true, true, true, false, 3><<<gb, 256>>>(
                        agg, Wlr, X[dt], Wrr, blr, nullptr, Y[dt], Nd);
                else
                    k_gemm<true, true, true, false, 2><<<gb, 256>>>(
                        agg, Wlr, X[dt], Wrr, blr, nullptr, Y[dt], Nd);
            }
        }
        for (int t = 0; t < 3; t++) {
            float* z = X[t];
            X[t] = Y[t];
            Y[t] = z;
        }
    }

    // projection head per type; output order: performance, artist, song
    // After 3 swaps X holds the final features and Y is dead scratch:
    // use Y[t] for the LN output and agg for the hidden activation.
    float* outp = (float*)d_out;
    float* outsec[3] = {outp, outp + (size_t)NPn * 128, outp + (size_t)(NPn + NAn) * 128};
    for (int t = 0; t < 3; t++) {
        int N = Nt[t];
        k_ln<<<(N * 32 + 255) / 256, 256>>>(X[t], lng + t * 128, lnb + t * 128, Y[t], N);
        k_gemm<true, false, true, false, 4><<<(N + 63) / 64, 256>>>(
            Y[t], pw1 + (size_t)t * 16384, nullptr, nullptr, pb1 + t * 128, nullptr, agg, N);
        k_gemm<true, false, true, false, 1><<<(N + 63) / 64, 256>>>(
            agg, pw2 + (size_t)t * 16384, nullptr, nullptr, pb2 + t * 128, nullptr, outsec[t], N);
    }
}

// round 5
// speedup vs baseline: 1.0146x; 1.0146x over previous
#include <cuda_runtime.h>
#include <math.h>
#include <stdint.h>

#define DD 128

static const int MAXP = 200000;
static const int MAXA = 30000;
static const int MAXS = 50000;
static const int MAXSRC = 50000;
static const int MAXE_TOT = 2000000;
static const int MAXN_TOT = 560000 + 64;

// ---------------- scratch (static __device__, no allocations) ----------------
__device__ float g_xp[MAXP * DD];
__device__ float g_xa[MAXA * DD];
__device__ float g_xs[MAXS * DD];
__device__ float g_yp[MAXP * DD];
__device__ float g_ya[MAXA * DD];
__device__ float g_ys[MAXS * DD];
__device__ float g_agg[MAXP * DD];
__device__ float g_tmp[MAXSRC * DD];
__device__ int g_rowptr[MAXN_TOT];
__device__ int g_cnt[MAXN_TOT];
__device__ int g_cursor[MAXN_TOT];
__device__ int g_srcs[MAXE_TOT];
__device__ int g_part[1024];

// ---------------- small helpers ----------------
__device__ __forceinline__ float4 ld4(const float* p) { return *reinterpret_cast<const float4*>(p); }
__device__ __forceinline__ void st4(float* p, float4 v) { *reinterpret_cast<float4*>(p) = v; }
__device__ __forceinline__ float2 ld2(const float* p) { return *reinterpret_cast<const float2*>(p); }
__device__ __forceinline__ void st2(float* p, float2 v) { *reinterpret_cast<float2*>(p) = v; }
__device__ __forceinline__ float4 f4add(float4 a, float4 b) {
    return make_float4(a.x + b.x, a.y + b.y, a.z + b.z, a.w + b.w);
}

// tf32 split: a = hi + lo with hi,lo tf32-representable (rna rounding)
__device__ __forceinline__ void split_tf32(float a, uint32_t& hi, uint32_t& lo) {
    asm("cvt.rna.tf32.f32 %0, %1;" : "=r"(hi) : "f"(a));
    float l = a - __uint_as_float(hi);
    asm("cvt.rna.tf32.f32 %0, %1;" : "=r"(lo) : "f"(l));
}

__device__ __forceinline__ void mma_tf32(float* c, const uint32_t* a, const uint32_t* b) {
    asm volatile(
        "mma.sync.aligned.m16n8k8.row.col.f32.tf32.tf32.f32 "
        "{%0,%1,%2,%3}, {%4,%5,%6,%7}, {%8,%9}, {%0,%1,%2,%3};"
        : "+f"(c[0]), "+f"(c[1]), "+f"(c[2]), "+f"(c[3])
        : "r"(a[0]), "r"(a[1]), "r"(a[2]), "r"(a[3]), "r"(b[0]), "r"(b[1]));
}

// ---------------- utility kernels ----------------
__global__ void k_zero(int* p, int n) {
    int i = blockIdx.x * blockDim.x + threadIdx.x;
    if (i < n) p[i] = 0;
}

__global__ void k_gather(const float* __restrict__ emb, const int* __restrict__ nid,
                         float* __restrict__ x, int n) {
    int i = blockIdx.x * blockDim.x + threadIdx.x;
    if (i < n * 32) {
        int r = i >> 5, c = i & 31;
        st4(x + (size_t)r * DD + c * 4, ld4(emb + (size_t)nid[r] * DD + c * 4));
    }
}

__global__ void k_count(const int* __restrict__ dst, int E, int* cnt) {
    int e = blockIdx.x * blockDim.x + threadIdx.x;
    if (e < E) atomicAdd(&cnt[dst[e]], 1);
}

__global__ void k_scan1(const int* __restrict__ cnt, int* __restrict__ rowptr,
                        int* __restrict__ part, int N) {
    __shared__ int s[512];
    int tid = threadIdx.x;
    int i = blockIdx.x * 512 + tid;
    int v = (i < N) ? cnt[i] : 0;
    s[tid] = v;
    __syncthreads();
    for (int off = 1; off < 512; off <<= 1) {
        int t = (tid >= off) ? s[tid - off] : 0;
        __syncthreads();
        s[tid] += t;
        __syncthreads();
    }
    if (i < N) rowptr[i] = s[tid] - v;
    if (tid == 511) part[blockIdx.x] = s[511];
}

__global__ void k_scan2(int* part, int n) {
    __shared__ int s[512];
    int tid = threadIdx.x;
    int v = (tid < n) ? part[tid] : 0;
    s[tid] = v;
    __syncthreads();
    for (int off = 1; off < 512; off <<= 1) {
        int t = (tid >= off) ? s[tid - off] : 0;
        __syncthreads();
        s[tid] += t;
        __syncthreads();
    }
    if (tid < n) part[tid] = s[tid] - v;
}

__global__ void k_scan3(int* rowptr, const int* __restrict__ part, int N) {
    int i = blockIdx.x * blockDim.x + threadIdx.x;
    if (i < N) rowptr[i] += part[i >> 9];
}

__global__ void k_scatter(const int* __restrict__ src, const int* __restrict__ dst, int E,
                          const int* __restrict__ rowptr, int* __restrict__ cursor,
                          int* __restrict__ out) {
    int e = blockIdx.x * blockDim.x + threadIdx.x;
    if (e < E) {
        int d = dst[e];
        int pos = rowptr[d] + atomicAdd(&cursor[d], 1);
        out[pos] = src[e];
    }
}

// segment-mean gather: one warp per destination row
__global__ void k_agg(const float* __restrict__ feat, const int* __restrict__ rowptr,
                      const int* __restrict__ cnt, const int* __restrict__ srcs,
                      float* __restrict__ out, int N) {
    int warp = (blockIdx.x * blockDim.x + threadIdx.x) >> 5;
    if (warp >= N) return;
    int lane = threadIdx.x & 31;
    int beg = rowptr[warp], n = cnt[warp];
    float4 acc = make_float4(0.f, 0.f, 0.f, 0.f);
    int i = 0;
    for (; i + 4 <= n; i += 4) {
        int s0 = srcs[beg + i], s1 = srcs[beg + i + 1];
        int s2 = srcs[beg + i + 2], s3 = srcs[beg + i + 3];
        float4 v0 = ld4(feat + (size_t)s0 * DD + lane * 4);
        float4 v1 = ld4(feat + (size_t)s1 * DD + lane * 4);
        float4 v2 = ld4(feat + (size_t)s2 * DD + lane * 4);
        float4 v3 = ld4(feat + (size_t)s3 * DD + lane * 4);
        acc = f4add(acc, f4add(f4add(v0, v1), f4add(v2, v3)));
    }
    for (; i < n; i++) {
        int s = srcs[beg + i];
        acc = f4add(acc, ld4(feat + (size_t)s * DD + lane * 4));
    }
    float inv = 1.0f / (float)max(n, 1);
    acc.x *= inv; acc.y *= inv; acc.z *= inv; acc.w *= inv;
    st4(out + (size_t)warp * DD + lane * 4, acc);
}

// layernorm: one warp per row
__global__ void k_ln(const float* __restrict__ x, const float* __restrict__ g,
                     const float* __restrict__ b, float* __restrict__ y, int N) {
    int warp = (blockIdx.x * blockDim.x + threadIdx.x) >> 5;
    if (warp >= N) return;
    int lane = threadIdx.x & 31;
    float4 v = ld4(x + (size_t)warp * DD + lane * 4);
    float s = v.x + v.y + v.z + v.w;
#pragma unroll
    for (int m = 16; m > 0; m >>= 1) s += __shfl_xor_sync(0xffffffffu, s, m);
    float mu = s * (1.0f / 128.0f);
    float4 d = make_float4(v.x - mu, v.y - mu, v.z - mu, v.w - mu);
    float ss = d.x * d.x + d.y * d.y + d.z * d.z + d.w * d.w;
#pragma unroll
    for (int m = 16; m > 0; m >>= 1) ss += __shfl_xor_sync(0xffffffffu, ss, m);
    float sc = rsqrtf(ss * (1.0f / 128.0f) + 1e-5f);
    float4 gv = ld4(g + lane * 4), bv = ld4(b + lane * 4);
    float4 o = make_float4(d.x * sc * gv.x + bv.x, d.y * sc * gv.y + bv.y,
                           d.z * sc * gv.z + bv.z, d.w * sc * gv.w + bv.w);
    st4(y + (size_t)warp * DD + lane * 4, o);
}

// ---------------- tensor-core fused GEMM (3xTF32 split, fp32-level accuracy) ----------------
// h = (U1 ? A1@W1 : 0) + (U2 ? A2@W2 : 0) + (HASPASS ? pass : 0) + (HASB ? bias : 0)
// EPI: 0 = store; 1 = l2norm store; 2 = l2norm add; 3 = l2norm add + relu; 4 = relu store
// Block tile 128 rows x 128 cols; 8 warps in 2(m) x 4(n); each warp 64x32.
// K chunked by 32 through smem; dual-source = second K pass.
template <bool U1, bool U2, bool HASB, bool HASPASS, int EPI>
__global__ void __launch_bounds__(256)
k_gemm(const float* __restrict__ A1, const float* __restrict__ W1,
       const float* __restrict__ A2, const float* __restrict__ W2,
       const float* __restrict__ bias, const float* __restrict__ pass,
       float* __restrict__ out, int N) {
    __shared__ float sA[128 * 40];    // row stride 40: frag-load banks (8g+t) conflict-free
    __shared__ float sW[32 * 136];    // row stride 136: frag-load banks (8t+g) conflict-free
    __shared__ float red[4 * 128];    // per-warpN row ssq partials

    const int tid = threadIdx.x;
    const int warp = tid >> 5;
    const int lane = tid & 31;
    const int warpM = warp >> 2;      // 0..1  -> rows  warpM*64
    const int warpN = warp & 3;       // 0..3  -> cols  warpN*32
    const int g = lane >> 2;          // groupID 0..7
    const int t = lane & 3;           // thread-in-group 0..3
    const int row0 = blockIdx.x * 128;

    float Cr[4][4][4];                // [mt][nt][frag]
#pragma unroll
    for (int mt = 0; mt < 4; mt++)
#pragma unroll
        for (int nt = 0; nt < 4; nt++)
#pragma unroll
            for (int j = 0; j < 4; j++) Cr[mt][nt][j] = 0.f;

#pragma unroll
    for (int s = 0; s < 2; s++) {
        if ((s == 0 && !U1) || (s == 1 && !U2)) continue;
        const float* Ap = (s == 0) ? A1 : A2;
        const float* Wp = (s == 0) ? W1 : W2;

        for (int k0 = 0; k0 < 128; k0 += 32) {
            __syncthreads();
            // load A tile: 128 rows x 32 k = 1024 float4
#pragma unroll
            for (int i = 0; i < 4; i++) {
                int idx = tid + i * 256;
                int r = idx >> 3, c4 = idx & 7;
                int grow = row0 + r;
                float4 v = make_float4(0.f, 0.f, 0.f, 0.f);
                if (grow < N) v = ld4(Ap + (size_t)grow * 128 + k0 + c4 * 4);
                st4(sA + r * 40 + c4 * 4, v);
            }
            // load W tile: 32 k x 128 cols = 1024 float4
#pragma unroll
            for (int i = 0; i < 4; i++) {
                int idx = tid + i * 256;
                int r = idx >> 5, c4 = idx & 31;
                st4(sW + r * 136 + c4 * 4, ld4(Wp + (size_t)(k0 + r) * 128 + c4 * 4));
            }
            __syncthreads();

#pragma unroll
            for (int kk = 0; kk < 4; kk++) {
                uint32_t bHi[4][2], bLo[4][2];
#pragma unroll
                for (int nt = 0; nt < 4; nt++) {
                    int n0 = warpN * 32 + nt * 8 + g;
                    float b0 = sW[(kk * 8 + t) * 136 + n0];
                    float b1 = sW[(kk * 8 + t + 4) * 136 + n0];
                    split_tf32(b0, bHi[nt][0], bLo[nt][0]);
                    split_tf32(b1, bHi[nt][1], bLo[nt][1]);
                }
#pragma unroll
                for (int mt = 0; mt < 4; mt++) {
                    int rb = warpM * 64 + mt * 16 + g;
                    uint32_t aHi[4], aLo[4];
                    float a0 = sA[rb * 40 + kk * 8 + t];
                    float a1 = sA[(rb + 8) * 40 + kk * 8 + t];
                    float a2 = sA[rb * 40 + kk * 8 + t + 4];
                    float a3 = sA[(rb + 8) * 40 + kk * 8 + t + 4];
                    split_tf32(a0, aHi[0], aLo[0]);
                    split_tf32(a1, aHi[1], aLo[1]);
                    split_tf32(a2, aHi[2], aLo[2]);
                    split_tf32(a3, aHi[3], aLo[3]);
#pragma unroll
                    for (int nt = 0; nt < 4; nt++) {
                        mma_tf32(Cr[mt][nt], aHi, bHi[nt]);
                        mma_tf32(Cr[mt][nt], aLo, bHi[nt]);
                        mma_tf32(Cr[mt][nt], aHi, bLo[nt]);
                    }
                }
            }
        }
    }

    // ---- epilogue ----
    float2 bv[4];
    if constexpr (HASB) {
#pragma unroll
        for (int nt = 0; nt < 4; nt++) bv[nt] = ld2(bias + warpN * 32 + nt * 8 + 2 * t);
    }

#pragma unroll
    for (int mt = 0; mt < 4; mt++) {
        int gr0 = row0 + warpM * 64 + mt * 16 + g;
        int gr1 = gr0 + 8;
        bool v0 = gr0 < N, v1 = gr1 < N;
#pragma unroll
        for (int nt = 0; nt < 4; nt++) {
            int col = warpN * 32 + nt * 8 + 2 * t;
            if constexpr (HASPASS) {
                if (v0) {
                    float2 p = ld2(pass + (size_t)gr0 * 128 + col);
                    Cr[mt][nt][0] += p.x; Cr[mt][nt][1] += p.y;
                }
                if (v1) {
                    float2 p = ld2(pass + (size_t)gr1 * 128 + col);
                    Cr[mt][nt][2] += p.x; Cr[mt][nt][3] += p.y;
                }
            }
            if constexpr (HASB) {
                Cr[mt][nt][0] += bv[nt].x; Cr[mt][nt][1] += bv[nt].y;
                Cr[mt][nt][2] += bv[nt].x; Cr[mt][nt][3] += bv[nt].y;
            }
        }
    }

    if constexpr (EPI == 0 || EPI == 4) {
#pragma unroll
        for (int mt = 0; mt < 4; mt++) {
            int gr0 = row0 + warpM * 64 + mt * 16 + g;
            int gr1 = gr0 + 8;
#pragma unroll
            for (int nt = 0; nt < 4; nt++) {
                int col = warpN * 32 + nt * 8 + 2 * t;
                float2 u0 = make_float2(Cr[mt][nt][0], Cr[mt][nt][1]);
                float2 u1 = make_float2(Cr[mt][nt][2], Cr[mt][nt][3]);
                if constexpr (EPI == 4) {
                    u0.x = fmaxf(u0.x, 0.f); u0.y = fmaxf(u0.y, 0.f);
                    u1.x = fmaxf(u1.x, 0.f); u1.y = fmaxf(u1.y, 0.f);
                }
                if (gr0 < N) st2(out + (size_t)gr0 * 128 + col, u0);
                if (gr1 < N) st2(out + (size_t)gr1 * 128 + col, u1);
            }
        }
    } else {
        // per-row sum of squares -> cross-warpN reduction in smem
#pragma unroll
        for (int mt = 0; mt < 4; mt++) {
            float s0 = 0.f, s1 = 0.f;
#pragma unroll
            for (int nt = 0; nt < 4; nt++) {
                s0 += Cr[mt][nt][0] * Cr[mt][nt][0] + Cr[mt][nt][1] * Cr[mt][nt][1];
                s1 += Cr[mt][nt][2] * Cr[mt][nt][2] + Cr[mt][nt][3] * Cr[mt][nt][3];
            }
            s0 += __shfl_xor_sync(0xffffffffu, s0, 1);
            s0 += __shfl_xor_sync(0xffffffffu, s0, 2);
            s1 += __shfl_xor_sync(0xffffffffu, s1, 1);
            s1 += __shfl_xor_sync(0xffffffffu, s1, 2);
            if (t == 0) {
                int lr = warpM * 64 + mt * 16 + g;
                red[warpN * 128 + lr] = s0;
                red[warpN * 128 + lr + 8] = s1;
            }
        }
        __syncthreads();
#pragma unroll
        for (int mt = 0; mt < 4; mt++) {
            int lr0 = warpM * 64 + mt * 16 + g;
            int lr1 = lr0 + 8;
            float q0 = red[lr0] + red[128 + lr0] + red[256 + lr0] + red[384 + lr0];
            float q1 = red[lr1] + red[128 + lr1] + red[256 + lr1] + red[384 + lr1];
            float sc0 = 1.0f / fmaxf(sqrtf(q0), 1e-12f);
            float sc1 = 1.0f / fmaxf(sqrtf(q1), 1e-12f);
            int gr0 = row0 + lr0, gr1 = row0 + lr1;
#pragma unroll
            for (int nt = 0; nt < 4; nt++) {
                int col = warpN * 32 + nt * 8 + 2 * t;
                float2 u0 = make_float2(Cr[mt][nt][0] * sc0, Cr[mt][nt][1] * sc0);
                float2 u1 = make_float2(Cr[mt][nt][2] * sc1, Cr[mt][nt][3] * sc1);
                if constexpr (EPI == 2 || EPI == 3) {
                    if (gr0 < N) {
                        float2 p = ld2(out + (size_t)gr0 * 128 + col);
                        u0.x += p.x; u0.y += p.y;
                    }
                    if (gr1 < N) {
                        float2 p = ld2(out + (size_t)gr1 * 128 + col);
                        u1.x += p.x; u1.y += p.y;
                    }
                    if constexpr (EPI == 3) {
                        u0.x = fmaxf(u0.x, 0.f); u0.y = fmaxf(u0.y, 0.f);
                        u1.x = fmaxf(u1.x, 0.f); u1.y = fmaxf(u1.y, 0.f);
                    }
                }
                if (gr0 < N) st2(out + (size_t)gr0 * 128 + col, u0);
                if (gr1 < N) st2(out + (size_t)gr1 * 128 + col, u1);
            }
        }
    }
}

// ---------------- host orchestration ----------------
extern "C" void kernel_launch(void* const* d_in, const int* in_sizes, int n_in,
                              void* d_out, int out_size) {
    const int* nidP = (const int*)d_in[0];
    const int* nidA = (const int*)d_in[1];
    const int* nidS = (const int*)d_in[2];
    const int* Eptr[6];
    int Ecnt[6];
    for (int r = 0; r < 6; r++) {
        Eptr[r] = (const int*)d_in[3 + r];
        Ecnt[r] = in_sizes[3 + r] / 2;
    }
    const float* embP = (const float*)d_in[9];
    const float* embA = (const float*)d_in[10];
    const float* embS = (const float*)d_in[11];
    const float* Wl = (const float*)d_in[12];
    const float* bl = (const float*)d_in[13];
    const float* Wr = (const float*)d_in[14];
    const float* lng = (const float*)d_in[15];
    const float* lnb = (const float*)d_in[16];
    const float* pw1 = (const float*)d_in[17];
    const float* pb1 = (const float*)d_in[18];
    const float* pw2 = (const float*)d_in[19];
    const float* pb2 = (const float*)d_in[20];
    int NPn = in_sizes[0], NAn = in_sizes[1], NSn = in_sizes[2];

    float *xp, *xa, *xs, *yp, *ya, *ys, *agg, *tmp;
    int *rowptr, *cnt, *cursor, *srcs, *part;
    cudaGetSymbolAddress((void**)&xp, g_xp);
    cudaGetSymbolAddress((void**)&xa, g_xa);
    cudaGetSymbolAddress((void**)&xs, g_xs);
    cudaGetSymbolAddress((void**)&yp, g_yp);
    cudaGetSymbolAddress((void**)&ya, g_ya);
    cudaGetSymbolAddress((void**)&ys, g_ys);
    cudaGetSymbolAddress((void**)&agg, g_agg);
    cudaGetSymbolAddress((void**)&tmp, g_tmp);
    cudaGetSymbolAddress((void**)&rowptr, g_rowptr);
    cudaGetSymbolAddress((void**)&cnt, g_cnt);
    cudaGetSymbolAddress((void**)&cursor, g_cursor);
    cudaGetSymbolAddress((void**)&srcs, g_srcs);
    cudaGetSymbolAddress((void**)&part, g_part);

    // relation meta: type ids: 0=perf,1=artist,2=song
    int Ndst[6] = {NPn, NSn, NSn, NAn, NPn, NAn};
    int dstT[6] = {0, 2, 2, 1, 0, 1};
    int srcT[6] = {1, 0, 1, 0, 2, 2};
    bool pre[6] = {true, false, true, false, true, false};  // transform at source?
    int roff[6], eoff[6];
    {
        int o = 0;
        for (int r = 0; r < 6; r++) { roff[r] = o; o += Ndst[r]; }
        o = 0;
        for (int r = 0; r < 6; r++) { eoff[r] = o; o += Ecnt[r]; }
    }

    // init features from embeddings
    k_gather<<<(NPn * 32 + 255) / 256, 256>>>(embP, nidP, xp, NPn);
    k_gather<<<(NAn * 32 + 255) / 256, 256>>>(embA, nidA, xa, NAn);
    k_gather<<<(NSn * 32 + 255) / 256, 256>>>(embS, nidS, xs, NSn);

    // build CSR per relation (edges are layer-invariant)
    for (int r = 0; r < 6; r++) {
        int Nd = Ndst[r], E = Ecnt[r];
        const int* srcp = Eptr[r];
        const int* dstp = Eptr[r] + E;
        int nb = (Nd + 511) / 512;
        k_zero<<<(Nd + 255) / 256, 256>>>(cnt + roff[r], Nd);
        k_zero<<<(Nd + 255) / 256, 256>>>(cursor + roff[r], Nd);
        k_count<<<(E + 255) / 256, 256>>>(dstp, E, cnt + roff[r]);
        k_scan1<<<nb, 512>>>(cnt + roff[r], rowptr + roff[r], part, Nd);
        k_scan2<<<1, 512>>>(part, nb);
        k_scan3<<<(Nd + 255) / 256, 256>>>(rowptr + roff[r], part, Nd);
        k_scatter<<<(E + 255) / 256, 256>>>(srcp, dstp, E, rowptr + roff[r], cursor + roff[r],
                                            srcs + eoff[r]);
    }

    float* X[3] = {xp, xa, xs};
    float* Y[3] = {yp, ya, ys};
    int Nt[3] = {NPn, NAn, NSn};
    int Ns_of[3] = {NPn, NAn, NSn};

    int order[6] = {0, 4, 1, 2, 3, 5};

    for (int layer = 0; layer < 3; layer++) {
        bool relu = (layer < 2);
        for (int oi = 0; oi < 6; oi++) {
            int r = order[oi];
            bool isFirst = (oi % 2 == 0);
            int Nd = Ndst[r];
            int st = srcT[r], dt = dstT[r];
            int Ns = Ns_of[st];
            const float* Wlr = Wl + ((size_t)layer * 6 + r) * 16384;
            const float* Wrr = Wr + ((size_t)layer * 6 + r) * 16384;
            const float* blr = bl + ((size_t)layer * 6 + r) * 128;
            int gb = (Nd + 127) / 128;
            int ab = (Nd * 32 + 255) / 256;
            if (pre[r]) {
                // tmp = X[src] @ Wl  (src side is artist or song: <= 50k rows)
                k_gemm<true, false, false, false, 0><<<(Ns + 127) / 128, 256>>>(
                    X[st], Wlr, nullptr, nullptr, nullptr, nullptr, tmp, Ns);
                k_agg<<<ab, 256>>>(tmp, rowptr + roff[r], cnt + roff[r], srcs + eoff[r], agg, Nd);
                if (isFirst)
                    k_gemm<false, true, true, true, 1><<<gb, 256>>>(
                        nullptr, nullptr, X[dt], Wrr, blr, agg, Y[dt], Nd);
                else if (relu)
                    k_gemm<false, true, true, true, 3><<<gb, 256>>>(
                        nullptr, nullptr, X[dt], Wrr, blr, agg, Y[dt], Nd);
                else
                    k_gemm<false, true, true, true, 2><<<gb, 256>>>(
                        nullptr, nullptr, X[dt], Wrr, blr, agg, Y[dt], Nd);
            } else {
                k_agg<<<ab, 256>>>(X[st], rowptr + roff[r], cnt + roff[r], srcs + eoff[r], agg, Nd);
                if (isFirst)
                    k_gemm<true, true, true, false, 1><<<gb, 256>>>(
                        agg, Wlr, X[dt], Wrr, blr, nullptr, Y[dt], Nd);
                else if (relu)
                    k_gemm<true, true, true, false, 3><<<gb, 256>>>(
                        agg, Wlr, X[dt], Wrr, blr, nullptr, Y[dt], Nd);
                else
                    k_gemm<true, true, true, false, 2><<<gb, 256>>>(
                        agg, Wlr, X[dt], Wrr, blr, nullptr, Y[dt], Nd);
            }
        }
        for (int t = 0; t < 3; t++) {
            float* z = X[t];
            X[t] = Y[t];
            Y[t] = z;
        }
    }

    // projection head per type; output order: performance, artist, song
    float* outp = (float*)d_out;
    float* outsec[3] = {outp, outp + (size_t)NPn * 128, outp + (size_t)(NPn + NAn) * 128};
    for (int t = 0; t < 3; t++) {
        int N = Nt[t];
        k_ln<<<(N * 32 + 255) / 256, 256>>>(X[t], lng + t * 128, lnb + t * 128, Y[t], N);
        k_gemm<true, false, true, false, 4><<<(N + 127) / 128, 256>>>(
            Y[t], pw1 + (size_t)t * 16384, nullptr, nullptr, pb1 + t * 128, nullptr, agg, N);
        k_gemm<true, false, true, false, 1><<<(N + 127) / 128, 256>>>(
            agg, pw2 + (size_t)t * 16384, nullptr, nullptr, pb2 + t * 128, nullptr, outsec[t], N);
    }
}

// round 7
// speedup vs baseline: 1.0931x; 1.0774x over previous
#include <cuda_runtime.h>
#include <math.h>
#include <stdint.h>

#define DD 128

static const int MAXP = 200000;
static const int MAXA = 30000;
static const int MAXS = 50000;
static const int MAXTMP = 110000;     // 30k (r0) + 30k (r2) + 50k (r4) slices
static const int MAXE_TOT = 2000000;
static const int MAXN_TOT = 560000 + 64;

// ---------------- scratch (static __device__, no allocations) ----------------
__device__ float g_xp[MAXP * DD];
__device__ float g_xa[MAXA * DD];
__device__ float g_xs[MAXS * DD];
__device__ float g_yp[MAXP * DD];
__device__ float g_ya[MAXA * DD];
__device__ float g_ys[MAXS * DD];
__device__ float g_agg[MAXP * DD];
__device__ float g_tmp[MAXTMP * DD];
__device__ int g_rowptr[MAXN_TOT];
__device__ int g_cnt[MAXN_TOT];
__device__ int g_cursor[MAXN_TOT];
__device__ int g_srcs[MAXE_TOT];
__device__ int g_part[1024];

// ---------------- small helpers ----------------
__device__ __forceinline__ float4 ld4(const float* p) { return *reinterpret_cast<const float4*>(p); }
__device__ __forceinline__ void st4(float* p, float4 v) { *reinterpret_cast<float4*>(p) = v; }
__device__ __forceinline__ float2 ld2(const float* p) { return *reinterpret_cast<const float2*>(p); }
__device__ __forceinline__ void st2(float* p, float2 v) { *reinterpret_cast<float2*>(p) = v; }
__device__ __forceinline__ float4 f4add(float4 a, float4 b) {
    return make_float4(a.x + b.x, a.y + b.y, a.z + b.z, a.w + b.w);
}

// tf32 split: a = hi + lo with hi,lo tf32-representable (rna rounding)
__device__ __forceinline__ void split_tf32(float a, uint32_t& hi, uint32_t& lo) {
    asm("cvt.rna.tf32.f32 %0, %1;" : "=r"(hi) : "f"(a));
    float l = a - __uint_as_float(hi);
    asm("cvt.rna.tf32.f32 %0, %1;" : "=r"(lo) : "f"(l));
}

__device__ __forceinline__ void mma_tf32(float* c, const uint32_t* a, const uint32_t* b) {
    asm volatile(
        "mma.sync.aligned.m16n8k8.row.col.f32.tf32.tf32.f32 "
        "{%0,%1,%2,%3}, {%4,%5,%6,%7}, {%8,%9}, {%0,%1,%2,%3};"
        : "+f"(c[0]), "+f"(c[1]), "+f"(c[2]), "+f"(c[3])
        : "r"(a[0]), "r"(a[1]), "r"(a[2]), "r"(a[3]), "r"(b[0]), "r"(b[1]));
}

// ---------------- utility kernels ----------------
__global__ void k_zero(int* p, int n) {
    int i = blockIdx.x * blockDim.x + threadIdx.x;
    if (i < n) p[i] = 0;
}

__global__ void k_gather(const float* __restrict__ emb, const int* __restrict__ nid,
                         float* __restrict__ x, int n) {
    int i = blockIdx.x * blockDim.x + threadIdx.x;
    if (i < n * 32) {
        int r = i >> 5, c = i & 31;
        st4(x + (size_t)r * DD + c * 4, ld4(emb + (size_t)nid[r] * DD + c * 4));
    }
}

__global__ void k_count(const int* __restrict__ dst, int E, int* cnt) {
    int e = blockIdx.x * blockDim.x + threadIdx.x;
    if (e < E) atomicAdd(&cnt[dst[e]], 1);
}

__global__ void k_scan1(const int* __restrict__ cnt, int* __restrict__ rowptr,
                        int* __restrict__ part, int N) {
    __shared__ int s[512];
    int tid = threadIdx.x;
    int i = blockIdx.x * 512 + tid;
    int v = (i < N) ? cnt[i] : 0;
    s[tid] = v;
    __syncthreads();
    for (int off = 1; off < 512; off <<= 1) {
        int t = (tid >= off) ? s[tid - off] : 0;
        __syncthreads();
        s[tid] += t;
        __syncthreads();
    }
    if (i < N) rowptr[i] = s[tid] - v;
    if (tid == 511) part[blockIdx.x] = s[511];
}

__global__ void k_scan2(int* part, int n) {
    __shared__ int s[512];
    int tid = threadIdx.x;
    int v = (tid < n) ? part[tid] : 0;
    s[tid] = v;
    __syncthreads();
    for (int off = 1; off < 512; off <<= 1) {
        int t = (tid >= off) ? s[tid - off] : 0;
        __syncthreads();
        s[tid] += t;
        __syncthreads();
    }
    if (tid < n) part[tid] = s[tid] - v;
}

__global__ void k_scan3(int* rowptr, const int* __restrict__ part, int N) {
    int i = blockIdx.x * blockDim.x + threadIdx.x;
    if (i < N) rowptr[i] += part[i >> 9];
}

__global__ void k_scatter(const int* __restrict__ src, const int* __restrict__ dst, int E,
                          const int* __restrict__ rowptr, int* __restrict__ cursor,
                          int* __restrict__ out) {
    int e = blockIdx.x * blockDim.x + threadIdx.x;
    if (e < E) {
        int d = dst[e];
        int pos = rowptr[d] + atomicAdd(&cursor[d], 1);
        out[pos] = src[e];
    }
}

// segment-mean gather: one warp per destination row
__global__ void k_agg(const float* __restrict__ feat, const int* __restrict__ rowptr,
                      const int* __restrict__ cnt, const int* __restrict__ srcs,
                      float* __restrict__ out, int N) {
    int warp = (blockIdx.x * blockDim.x + threadIdx.x) >> 5;
    if (warp >= N) return;
    int lane = threadIdx.x & 31;
    int beg = rowptr[warp], n = cnt[warp];
    float4 acc = make_float4(0.f, 0.f, 0.f, 0.f);
    int i = 0;
    for (; i + 4 <= n; i += 4) {
        int s0 = srcs[beg + i], s1 = srcs[beg + i + 1];
        int s2 = srcs[beg + i + 2], s3 = srcs[beg + i + 3];
        float4 v0 = ld4(feat + (size_t)s0 * DD + lane * 4);
        float4 v1 = ld4(feat + (size_t)s1 * DD + lane * 4);
        float4 v2 = ld4(feat + (size_t)s2 * DD + lane * 4);
        float4 v3 = ld4(feat + (size_t)s3 * DD + lane * 4);
        acc = f4add(acc, f4add(f4add(v0, v1), f4add(v2, v3)));
    }
    for (; i < n; i++) {
        int s = srcs[beg + i];
        acc = f4add(acc, ld4(feat + (size_t)s * DD + lane * 4));
    }
    float inv = 1.0f / (float)max(n, 1);
    acc.x *= inv; acc.y *= inv; acc.z *= inv; acc.w *= inv;
    st4(out + (size_t)warp * DD + lane * 4, acc);
}

// layernorm: one warp per row
__global__ void k_ln(const float* __restrict__ x, const float* __restrict__ g,
                     const float* __restrict__ b, float* __restrict__ y, int N) {
    int warp = (blockIdx.x * blockDim.x + threadIdx.x) >> 5;
    if (warp >= N) return;
    int lane = threadIdx.x & 31;
    float4 v = ld4(x + (size_t)warp * DD + lane * 4);
    float s = v.x + v.y + v.z + v.w;
#pragma unroll
    for (int m = 16; m > 0; m >>= 1) s += __shfl_xor_sync(0xffffffffu, s, m);
    float mu = s * (1.0f / 128.0f);
    float4 d = make_float4(v.x - mu, v.y - mu, v.z - mu, v.w - mu);
    float ss = d.x * d.x + d.y * d.y + d.z * d.z + d.w * d.w;
#pragma unroll
    for (int m = 16; m > 0; m >>= 1) ss += __shfl_xor_sync(0xffffffffu, ss, m);
    float sc = rsqrtf(ss * (1.0f / 128.0f) + 1e-5f);
    float4 gv = ld4(g + lane * 4), bv = ld4(b + lane * 4);
    float4 o = make_float4(d.x * sc * gv.x + bv.x, d.y * sc * gv.y + bv.y,
                           d.z * sc * gv.z + bv.z, d.w * sc * gv.w + bv.w);
    st4(y + (size_t)warp * DD + lane * 4, o);
}

// ---------------- tensor-core fused GEMM (3xTF32, splits precomputed at smem load) ----------
// h = (U1 ? A1@W1 : 0) + (U2 ? A2@W2 : 0) + (HASPASS ? pass : 0) + (HASB ? bias : 0)
// EPI: 0 = store; 1 = l2norm store; 2 = l2norm add; 3 = l2norm add + relu; 4 = relu store
// Block tile 128x128, 8 warps (2m x 4n), warp tile 64x32, K chunk 16.
template <bool U1, bool U2, bool HASB, bool HASPASS, int EPI>
__global__ void __launch_bounds__(256)
k_gemm(const float* __restrict__ A1, const float* __restrict__ W1,
       const float* __restrict__ A2, const float* __restrict__ W2,
       const float* __restrict__ bias, const float* __restrict__ pass,
       float* __restrict__ out, int N) {
    __shared__ uint32_t sAhi[128 * 20];   // stride 20: frag banks conflict-free
    __shared__ uint32_t sAlo[128 * 20];
    __shared__ uint32_t sWhi[16 * 136];   // stride 136: frag banks (8t+g) conflict-free
    __shared__ uint32_t sWlo[16 * 136];
    __shared__ float red[4 * 128];

    const int tid = threadIdx.x;
    const int warp = tid >> 5;
    const int lane = tid & 31;
    const int warpM = warp >> 2;
    const int warpN = warp & 3;
    const int g = lane >> 2;
    const int t = lane & 3;
    const int row0 = blockIdx.x * 128;

    float Cr[4][4][4];
#pragma unroll
    for (int mt = 0; mt < 4; mt++)
#pragma unroll
        for (int nt = 0; nt < 4; nt++)
#pragma unroll
            for (int j = 0; j < 4; j++) Cr[mt][nt][j] = 0.f;

#pragma unroll
    for (int s = 0; s < 2; s++) {
        if ((s == 0 && !U1) || (s == 1 && !U2)) continue;
        const float* Ap = (s == 0) ? A1 : A2;
        const float* Wp = (s == 0) ? W1 : W2;

        for (int k0 = 0; k0 < 128; k0 += 16) {
            __syncthreads();
            // A tile 128x16 = 512 float4, 2 per thread; split at store time
#pragma unroll
            for (int i = 0; i < 2; i++) {
                int idx = tid + i * 256;
                int r = idx >> 2, c4 = idx & 3;
                int grow = row0 + r;
                float4 v = make_float4(0.f, 0.f, 0.f, 0.f);
                if (grow < N) v = ld4(Ap + (size_t)grow * 128 + k0 + c4 * 4);
                uint4 h, l;
                split_tf32(v.x, h.x, l.x); split_tf32(v.y, h.y, l.y);
                split_tf32(v.z, h.z, l.z); split_tf32(v.w, h.w, l.w);
                *reinterpret_cast<uint4*>(sAhi + r * 20 + c4 * 4) = h;
                *reinterpret_cast<uint4*>(sAlo + r * 20 + c4 * 4) = l;
            }
            // W tile 16x128 = 512 float4, 2 per thread
#pragma unroll
            for (int i = 0; i < 2; i++) {
                int idx = tid + i * 256;
                int r = idx >> 5, c4 = idx & 31;
                float4 v = ld4(Wp + (size_t)(k0 + r) * 128 + c4 * 4);
                uint4 h, l;
                split_tf32(v.x, h.x, l.x); split_tf32(v.y, h.y, l.y);
                split_tf32(v.z, h.z, l.z); split_tf32(v.w, h.w, l.w);
                *reinterpret_cast<uint4*>(sWhi + r * 136 + c4 * 4) = h;
                *reinterpret_cast<uint4*>(sWlo + r * 136 + c4 * 4) = l;
            }
            __syncthreads();

#pragma unroll
            for (int kk = 0; kk < 2; kk++) {
                uint32_t bHi[4][2], bLo[4][2];
#pragma unroll
                for (int nt = 0; nt < 4; nt++) {
                    int n0 = warpN * 32 + nt * 8 + g;
                    bHi[nt][0] = sWhi[(kk * 8 + t) * 136 + n0];
                    bHi[nt][1] = sWhi[(kk * 8 + t + 4) * 136 + n0];
                    bLo[nt][0] = sWlo[(kk * 8 + t) * 136 + n0];
                    bLo[nt][1] = sWlo[(kk * 8 + t + 4) * 136 + n0];
                }
#pragma unroll
                for (int mt = 0; mt < 4; mt++) {
                    int rb = warpM * 64 + mt * 16 + g;
                    uint32_t aHi[4], aLo[4];
                    aHi[0] = sAhi[rb * 20 + kk * 8 + t];
                    aHi[1] = sAhi[(rb + 8) * 20 + kk * 8 + t];
                    aHi[2] = sAhi[rb * 20 + kk * 8 + t + 4];
                    aHi[3] = sAhi[(rb + 8) * 20 + kk * 8 + t + 4];
                    aLo[0] = sAlo[rb * 20 + kk * 8 + t];
                    aLo[1] = sAlo[(rb + 8) * 20 + kk * 8 + t];
                    aLo[2] = sAlo[rb * 20 + kk * 8 + t + 4];
                    aLo[3] = sAlo[(rb + 8) * 20 + kk * 8 + t + 4];
#pragma unroll
                    for (int nt = 0; nt < 4; nt++) {
                        mma_tf32(Cr[mt][nt], aHi, bHi[nt]);
                        mma_tf32(Cr[mt][nt], aLo, bHi[nt]);
                        mma_tf32(Cr[mt][nt], aHi, bLo[nt]);
                    }
                }
            }
        }
    }

    // ---- epilogue ----
    float2 bv[4];
    if constexpr (HASB) {
#pragma unroll
        for (int nt = 0; nt < 4; nt++) bv[nt] = ld2(bias + warpN * 32 + nt * 8 + 2 * t);
    }

#pragma unroll
    for (int mt = 0; mt < 4; mt++) {
        int gr0 = row0 + warpM * 64 + mt * 16 + g;
        int gr1 = gr0 + 8;
        bool v0 = gr0 < N, v1 = gr1 < N;
#pragma unroll
        for (int nt = 0; nt < 4; nt++) {
            int col = warpN * 32 + nt * 8 + 2 * t;
            if constexpr (HASPASS) {
                if (v0) {
                    float2 p = ld2(pass + (size_t)gr0 * 128 + col);
                    Cr[mt][nt][0] += p.x; Cr[mt][nt][1] += p.y;
                }
                if (v1) {
                    float2 p = ld2(pass + (size_t)gr1 * 128 + col);
                    Cr[mt][nt][2] += p.x; Cr[mt][nt][3] += p.y;
                }
            }
            if constexpr (HASB) {
                Cr[mt][nt][0] += bv[nt].x; Cr[mt][nt][1] += bv[nt].y;
                Cr[mt][nt][2] += bv[nt].x; Cr[mt][nt][3] += bv[nt].y;
            }
        }
    }

    if constexpr (EPI == 0 || EPI == 4) {
#pragma unroll
        for (int mt = 0; mt < 4; mt++) {
            int gr0 = row0 + warpM * 64 + mt * 16 + g;
            int gr1 = gr0 + 8;
#pragma unroll
            for (int nt = 0; nt < 4; nt++) {
                int col = warpN * 32 + nt * 8 + 2 * t;
                float2 u0 = make_float2(Cr[mt][nt][0], Cr[mt][nt][1]);
                float2 u1 = make_float2(Cr[mt][nt][2], Cr[mt][nt][3]);
                if constexpr (EPI == 4) {
                    u0.x = fmaxf(u0.x, 0.f); u0.y = fmaxf(u0.y, 0.f);
                    u1.x = fmaxf(u1.x, 0.f); u1.y = fmaxf(u1.y, 0.f);
                }
                if (gr0 < N) st2(out + (size_t)gr0 * 128 + col, u0);
                if (gr1 < N) st2(out + (size_t)gr1 * 128 + col, u1);
            }
        }
    } else {
#pragma unroll
        for (int mt = 0; mt < 4; mt++) {
            float s0 = 0.f, s1 = 0.f;
#pragma unroll
            for (int nt = 0; nt < 4; nt++) {
                s0 += Cr[mt][nt][0] * Cr[mt][nt][0] + Cr[mt][nt][1] * Cr[mt][nt][1];
                s1 += Cr[mt][nt][2] * Cr[mt][nt][2] + Cr[mt][nt][3] * Cr[mt][nt][3];
            }
            s0 += __shfl_xor_sync(0xffffffffu, s0, 1);
            s0 += __shfl_xor_sync(0xffffffffu, s0, 2);
            s1 += __shfl_xor_sync(0xffffffffu, s1, 1);
            s1 += __shfl_xor_sync(0xffffffffu, s1, 2);
            if (t == 0) {
                int lr = warpM * 64 + mt * 16 + g;
                red[warpN * 128 + lr] = s0;
                red[warpN * 128 + lr + 8] = s1;
            }
        }
        __syncthreads();
#pragma unroll
        for (int mt = 0; mt < 4; mt++) {
            int lr0 = warpM * 64 + mt * 16 + g;
            int lr1 = lr0 + 8;
            float q0 = red[lr0] + red[128 + lr0] + red[256 + lr0] + red[384 + lr0];
            float q1 = red[lr1] + red[128 + lr1] + red[256 + lr1] + red[384 + lr1];
            float sc0 = 1.0f / fmaxf(sqrtf(q0), 1e-12f);
            float sc1 = 1.0f / fmaxf(sqrtf(q1), 1e-12f);
            int gr0 = row0 + lr0, gr1 = row0 + lr1;
#pragma unroll
            for (int nt = 0; nt < 4; nt++) {
                int col = warpN * 32 + nt * 8 + 2 * t;
                float2 u0 = make_float2(Cr[mt][nt][0] * sc0, Cr[mt][nt][1] * sc0);
                float2 u1 = make_float2(Cr[mt][nt][2] * sc1, Cr[mt][nt][3] * sc1);
                if constexpr (EPI == 2 || EPI == 3) {
                    if (gr0 < N) {
                        float2 p = ld2(out + (size_t)gr0 * 128 + col);
                        u0.x += p.x; u0.y += p.y;
                    }
                    if (gr1 < N) {
                        float2 p = ld2(out + (size_t)gr1 * 128 + col);
                        u1.x += p.x; u1.y += p.y;
                    }
                    if constexpr (EPI == 3) {
                        u0.x = fmaxf(u0.x, 0.f); u0.y = fmaxf(u0.y, 0.f);
                        u1.x = fmaxf(u1.x, 0.f); u1.y = fmaxf(u1.y, 0.f);
                    }
                }
                if (gr0 < N) st2(out + (size_t)gr0 * 128 + col, u0);
                if (gr1 < N) st2(out + (size_t)gr1 * 128 + col, u1);
            }
        }
    }
}

// ---------------- host orchestration ----------------
extern "C" void kernel_launch(void* const* d_in, const int* in_sizes, int n_in,
                              void* d_out, int out_size) {
    const int* nidP = (const int*)d_in[0];
    const int* nidA = (const int*)d_in[1];
    const int* nidS = (const int*)d_in[2];
    const int* Eptr[6];
    int Ecnt[6];
    for (int r = 0; r < 6; r++) {
        Eptr[r] = (const int*)d_in[3 + r];
        Ecnt[r] = in_sizes[3 + r] / 2;
    }
    const float* embP = (const float*)d_in[9];
    const float* embA = (const float*)d_in[10];
    const float* embS = (const float*)d_in[11];
    const float* Wl = (const float*)d_in[12];
    const float* bl = (const float*)d_in[13];
    const float* Wr = (const float*)d_in[14];
    const float* lng = (const float*)d_in[15];
    const float* lnb = (const float*)d_in[16];
    const float* pw1 = (const float*)d_in[17];
    const float* pb1 = (const float*)d_in[18];
    const float* pw2 = (const float*)d_in[19];
    const float* pb2 = (const float*)d_in[20];
    int NPn = in_sizes[0], NAn = in_sizes[1], NSn = in_sizes[2];

    float *xp, *xa, *xs, *yp, *ya, *ys, *agg, *tmp;
    int *rowptr, *cnt, *cursor, *srcs, *part;
    cudaGetSymbolAddress((void**)&xp, g_xp);
    cudaGetSymbolAddress((void**)&xa, g_xa);
    cudaGetSymbolAddress((void**)&xs, g_xs);
    cudaGetSymbolAddress((void**)&yp, g_yp);
    cudaGetSymbolAddress((void**)&ya, g_ya);
    cudaGetSymbolAddress((void**)&ys, g_ys);
    cudaGetSymbolAddress((void**)&agg, g_agg);
    cudaGetSymbolAddress((void**)&tmp, g_tmp);
    cudaGetSymbolAddress((void**)&rowptr, g_rowptr);
    cudaGetSymbolAddress((void**)&cnt, g_cnt);
    cudaGetSymbolAddress((void**)&cursor, g_cursor);
    cudaGetSymbolAddress((void**)&srcs, g_srcs);
    cudaGetSymbolAddress((void**)&part, g_part);

    // relation meta: type ids: 0=perf,1=artist,2=song
    int Ndst[6] = {NPn, NSn, NSn, NAn, NPn, NAn};
    int dstT[6] = {0, 2, 2, 1, 0, 1};
    int srcT[6] = {1, 0, 1, 0, 2, 2};
    bool pre[6] = {true, false, true, false, true, false};
    // layer-0 pre-transform tmp slice offsets (rows): r0->0, r2->NAn, r4->2*NAn
    size_t tmpoff[6] = {0, 0, (size_t)NAn * DD, 0, (size_t)2 * NAn * DD, 0};
    int roff[6], eoff[6];
    int rsum = 0;
    {
        int o = 0;
        for (int r = 0; r < 6; r++) { roff[r] = o; o += Ndst[r]; }
        rsum = o;
        o = 0;
        for (int r = 0; r < 6; r++) { eoff[r] = o; o += Ecnt[r]; }
    }

    float* X[3] = {xp, xa, xs};
    float* Y[3] = {yp, ya, ys};
    int Nt[3] = {NPn, NAn, NSn};

    // launches 1-3: init features from embeddings
    k_gather<<<(NPn * 32 + 255) / 256, 256>>>(embP, nidP, xp, NPn);
    k_gather<<<(NAn * 32 + 255) / 256, 256>>>(embA, nidA, xa, NAn);
    k_gather<<<(NSn * 32 + 255) / 256, 256>>>(embS, nidS, xs, NSn);

    // launches 4-6: layer-0 pre-transform GEMMs (hoisted so ncu -s 5 captures a GEMM)
    {
        int prerels[3] = {0, 2, 4};
        for (int i = 0; i < 3; i++) {
            int r = prerels[i];
            int st = srcT[r];
            int Ns = Nt[st];
            const float* Wlr = Wl + ((size_t)0 * 6 + r) * 16384;
            k_gemm<true, false, false, false, 0><<<(Ns + 127) / 128, 256>>>(
                X[st], Wlr, nullptr, nullptr, nullptr, nullptr, tmp + tmpoff[r], Ns);
        }
    }

    // bulk-zero CSR counters, then build CSR per relation (layer-invariant)
    k_zero<<<(rsum + 255) / 256, 256>>>(cnt, rsum);
    k_zero<<<(rsum + 255) / 256, 256>>>(cursor, rsum);
    for (int r = 0; r < 6; r++) {
        int Nd = Ndst[r], E = Ecnt[r];
        const int* srcp = Eptr[r];
        const int* dstp = Eptr[r] + E;
        int nb = (Nd + 511) / 512;
        k_count<<<(E + 255) / 256, 256>>>(dstp, E, cnt + roff[r]);
        k_scan1<<<nb, 512>>>(cnt + roff[r], rowptr + roff[r], part, Nd);
        k_scan2<<<1, 512>>>(part, nb);
        k_scan3<<<(Nd + 255) / 256, 256>>>(rowptr + roff[r], part, Nd);
        k_scatter<<<(E + 255) / 256, 256>>>(srcp, dstp, E, rowptr + roff[r], cursor + roff[r],
                                            srcs + eoff[r]);
    }

    int order[6] = {0, 4, 1, 2, 3, 5};

    for (int layer = 0; layer < 3; layer++) {
        bool relu = (layer < 2);
        for (int oi = 0; oi < 6; oi++) {
            int r = order[oi];
            bool isFirst = (oi % 2 == 0);
            int Nd = Ndst[r];
            int st = srcT[r], dt = dstT[r];
            int Ns = Nt[st];
            const float* Wlr = Wl + ((size_t)layer * 6 + r) * 16384;
            const float* Wrr = Wr + ((size_t)layer * 6 + r) * 16384;
            const float* blr = bl + ((size_t)layer * 6 + r) * 128;
            int gb = (Nd + 127) / 128;
            int ab = (Nd * 32 + 255) / 256;
            if (pre[r]) {
                float* tsl = (layer == 0) ? (tmp + tmpoff[r]) : tmp;
                if (layer != 0) {
                    k_gemm<true, false, false, false, 0><<<(Ns + 127) / 128, 256>>>(
                        X[st], Wlr, nullptr, nullptr, nullptr, nullptr, tsl, Ns);
                }
                k_agg<<<ab, 256>>>(tsl, rowptr + roff[r], cnt + roff[r], srcs + eoff[r], agg, Nd);
                if (isFirst)
                    k_gemm<false, true, true, true, 1><<<gb, 256>>>(
                        nullptr, nullptr, X[dt], Wrr, blr, agg, Y[dt], Nd);
                else if (relu)
                    k_gemm<false, true, true, true, 3><<<gb, 256>>>(
                        nullptr, nullptr, X[dt], Wrr, blr, agg, Y[dt], Nd);
                else
                    k_gemm<false, true, true, true, 2><<<gb, 256>>>(
                        nullptr, nullptr, X[dt], Wrr, blr, agg, Y[dt], Nd);
            } else {
                k_agg<<<ab, 256>>>(X[st], rowptr + roff[r], cnt + roff[r], srcs + eoff[r], agg, Nd);
                if (isFirst)
                    k_gemm<true, true, true, false, 1><<<gb, 256>>>(
                        agg, Wlr, X[dt], Wrr, blr, nullptr, Y[dt], Nd);
                else if (relu)
                    k_gemm<true, true, true, false, 3><<<gb, 256>>>(
                        agg, Wlr, X[dt], Wrr, blr, nullptr, Y[dt], Nd);
                else
                    k_gemm<true, true, true, false, 2><<<gb, 256>>>(
                        agg, Wlr, X[dt], Wrr, blr, nullptr, Y[dt], Nd);
            }
        }
        for (int t = 0; t < 3; t++) {
            float* z = X[t];
            X[t] = Y[t];
            Y[t] = z;
        }
    }

    // projection head per type; output order: performance, artist, song
    float* outp = (float*)d_out;
    float* outsec[3] = {outp, outp + (size_t)NPn * 128, outp + (size_t)(NPn + NAn) * 128};
    for (int t = 0; t < 3; t++) {
        int N = Nt[t];
        k_ln<<<(N * 32 + 255) / 256, 256>>>(X[t], lng + t * 128, lnb + t * 128, Y[t], N);
        k_gemm<true, false, true, false, 4><<<(N + 127) / 128, 256>>>(
            Y[t], pw1 + (size_t)t * 16384, nullptr, nullptr, pb1 + t * 128, nullptr, agg, N);
        k_gemm<true, false, true, false, 1><<<(N + 127) / 128, 256>>>(
            agg, pw2 + (size_t)t * 16384, nullptr, nullptr, pb2 + t * 128, nullptr, outsec[t], N);
    }
}

// round 8
// speedup vs baseline: 1.2724x; 1.1640x over previous
#include <cuda_runtime.h>
#include <math.h>
#include <stdint.h>

#define DD 128

static const int MAXP = 200000;
static const int MAXA = 30000;
static const int MAXS = 50000;
static const int MAXTMP = 110000;     // 30k (r0) + 30k (r2) + 50k (r4) slices
static const int MAXE_TOT = 2000000;
static const int MAXN_TOT = 560000 + 64;

// ---------------- scratch (static __device__, no allocations) ----------------
__device__ float g_xp[MAXP * DD];
__device__ float g_xa[MAXA * DD];
__device__ float g_xs[MAXS * DD];
__device__ float g_yp[MAXP * DD];
__device__ float g_ya[MAXA * DD];
__device__ float g_ys[MAXS * DD];
__device__ float g_agg[MAXP * DD];
__device__ float g_tmp[MAXTMP * DD];
__device__ int g_rowptr[MAXN_TOT];
__device__ int g_cnt[MAXN_TOT];
__device__ int g_cursor[MAXN_TOT];
__device__ int g_srcs[MAXE_TOT];
__device__ int g_part[1024];

// ---------------- small helpers ----------------
__device__ __forceinline__ float4 ld4(const float* p) { return *reinterpret_cast<const float4*>(p); }
__device__ __forceinline__ void st4(float* p, float4 v) { *reinterpret_cast<float4*>(p) = v; }
__device__ __forceinline__ float2 ld2(const float* p) { return *reinterpret_cast<const float2*>(p); }
__device__ __forceinline__ void st2(float* p, float2 v) { *reinterpret_cast<float2*>(p) = v; }
__device__ __forceinline__ float4 f4add(float4 a, float4 b) {
    return make_float4(a.x + b.x, a.y + b.y, a.z + b.z, a.w + b.w);
}

// tf32 split: a = hi + lo with hi,lo tf32-representable (rna rounding)
__device__ __forceinline__ void split_tf32(float a, uint32_t& hi, uint32_t& lo) {
    asm("cvt.rna.tf32.f32 %0, %1;" : "=r"(hi) : "f"(a));
    float l = a - __uint_as_float(hi);
    asm("cvt.rna.tf32.f32 %0, %1;" : "=r"(lo) : "f"(l));
}

__device__ __forceinline__ void mma_tf32(float* c, const uint32_t* a, const uint32_t* b) {
    asm volatile(
        "mma.sync.aligned.m16n8k8.row.col.f32.tf32.tf32.f32 "
        "{%0,%1,%2,%3}, {%4,%5,%6,%7}, {%8,%9}, {%0,%1,%2,%3};"
        : "+f"(c[0]), "+f"(c[1]), "+f"(c[2]), "+f"(c[3])
        : "r"(a[0]), "r"(a[1]), "r"(a[2]), "r"(a[3]), "r"(b[0]), "r"(b[1]));
}

// ---------------- utility kernels ----------------
__global__ void k_zero(int* p, int n) {
    int i = blockIdx.x * blockDim.x + threadIdx.x;
    if (i < n) p[i] = 0;
}

__global__ void k_gather(const float* __restrict__ emb, const int* __restrict__ nid,
                         float* __restrict__ x, int n) {
    int i = blockIdx.x * blockDim.x + threadIdx.x;
    if (i < n * 32) {
        int r = i >> 5, c = i & 31;
        st4(x + (size_t)r * DD + c * 4, ld4(emb + (size_t)nid[r] * DD + c * 4));
    }
}

__global__ void k_count(const int* __restrict__ dst, int E, int* cnt) {
    int e = blockIdx.x * blockDim.x + threadIdx.x;
    if (e < E) atomicAdd(&cnt[dst[e]], 1);
}

__global__ void k_scan1(const int* __restrict__ cnt, int* __restrict__ rowptr,
                        int* __restrict__ part, int N) {
    __shared__ int s[512];
    int tid = threadIdx.x;
    int i = blockIdx.x * 512 + tid;
    int v = (i < N) ? cnt[i] : 0;
    s[tid] = v;
    __syncthreads();
    for (int off = 1; off < 512; off <<= 1) {
        int t = (tid >= off) ? s[tid - off] : 0;
        __syncthreads();
        s[tid] += t;
        __syncthreads();
    }
    if (i < N) rowptr[i] = s[tid] - v;
    if (tid == 511) part[blockIdx.x] = s[511];
}

__global__ void k_scan2(int* part, int n) {
    __shared__ int s[512];
    int tid = threadIdx.x;
    int v = (tid < n) ? part[tid] : 0;
    s[tid] = v;
    __syncthreads();
    for (int off = 1; off < 512; off <<= 1) {
        int t = (tid >= off) ? s[tid - off] : 0;
        __syncthreads();
        s[tid] += t;
        __syncthreads();
    }
    if (tid < n) part[tid] = s[tid] - v;
}

__global__ void k_scan3(int* rowptr, const int* __restrict__ part, int N) {
    int i = blockIdx.x * blockDim.x + threadIdx.x;
    if (i < N) rowptr[i] += part[i >> 9];
}

__global__ void k_scatter(const int* __restrict__ src, const int* __restrict__ dst, int E,
                          const int* __restrict__ rowptr, int* __restrict__ cursor,
                          int* __restrict__ out) {
    int e = blockIdx.x * blockDim.x + threadIdx.x;
    if (e < E) {
        int d = dst[e];
        int pos = rowptr[d] + atomicAdd(&cursor[d], 1);
        out[pos] = src[e];
    }
}

// segment-mean gather: one warp per destination row
__global__ void k_agg(const float* __restrict__ feat, const int* __restrict__ rowptr,
                      const int* __restrict__ cnt, const int* __restrict__ srcs,
                      float* __restrict__ out, int N) {
    int warp = (blockIdx.x * blockDim.x + threadIdx.x) >> 5;
    if (warp >= N) return;
    int lane = threadIdx.x & 31;
    int beg = rowptr[warp], n = cnt[warp];
    float4 acc = make_float4(0.f, 0.f, 0.f, 0.f);
    int i = 0;
    for (; i + 4 <= n; i += 4) {
        int s0 = srcs[beg + i], s1 = srcs[beg + i + 1];
        int s2 = srcs[beg + i + 2], s3 = srcs[beg + i + 3];
        float4 v0 = ld4(feat + (size_t)s0 * DD + lane * 4);
        float4 v1 = ld4(feat + (size_t)s1 * DD + lane * 4);
        float4 v2 = ld4(feat + (size_t)s2 * DD + lane * 4);
        float4 v3 = ld4(feat + (size_t)s3 * DD + lane * 4);
        acc = f4add(acc, f4add(f4add(v0, v1), f4add(v2, v3)));
    }
    for (; i < n; i++) {
        int s = srcs[beg + i];
        acc = f4add(acc, ld4(feat + (size_t)s * DD + lane * 4));
    }
    float inv = 1.0f / (float)max(n, 1);
    acc.x *= inv; acc.y *= inv; acc.z *= inv; acc.w *= inv;
    st4(out + (size_t)warp * DD + lane * 4, acc);
}

// layernorm: one warp per row
__global__ void k_ln(const float* __restrict__ x, const float* __restrict__ g,
                     const float* __restrict__ b, float* __restrict__ y, int N) {
    int warp = (blockIdx.x * blockDim.x + threadIdx.x) >> 5;
    if (warp >= N) return;
    int lane = threadIdx.x & 31;
    float4 v = ld4(x + (size_t)warp * DD + lane * 4);
    float s = v.x + v.y + v.z + v.w;
#pragma unroll
    for (int m = 16; m > 0; m >>= 1) s += __shfl_xor_sync(0xffffffffu, s, m);
    float mu = s * (1.0f / 128.0f);
    float4 d = make_float4(v.x - mu, v.y - mu, v.z - mu, v.w - mu);
    float ss = d.x * d.x + d.y * d.y + d.z * d.z + d.w * d.w;
#pragma unroll
    for (int m = 16; m > 0; m >>= 1) ss += __shfl_xor_sync(0xffffffffu, ss, m);
    float sc = rsqrtf(ss * (1.0f / 128.0f) + 1e-5f);
    float4 gv = ld4(g + lane * 4), bv = ld4(b + lane * 4);
    float4 o = make_float4(d.x * sc * gv.x + bv.x, d.y * sc * gv.y + bv.y,
                           d.z * sc * gv.z + bv.z, d.w * sc * gv.w + bv.w);
    st4(y + (size_t)warp * DD + lane * 4, o);
}

// ---------------- tensor-core fused GEMM (3xTF32, double-buffered pipeline) --------------
// h = (U1 ? A1@W1 : 0) + (U2 ? A2@W2 : 0) + (HASPASS ? pass : 0) + (HASB ? bias : 0)
// EPI: 0 = store; 1 = l2norm store; 2 = l2norm add; 3 = l2norm add + relu; 4 = relu store
// Block tile 128x128, 8 warps (2m x 4n), warp tile 64x32, K chunk 8, 2 smem buffers.
template <bool U1, bool U2, bool HASB, bool HASPASS, int EPI>
__global__ void __launch_bounds__(256, 2)
k_gemm(const float* __restrict__ A1, const float* __restrict__ W1,
       const float* __restrict__ A2, const float* __restrict__ W2,
       const float* __restrict__ bias, const float* __restrict__ pass,
       float* __restrict__ out, int N) {
    // A plane: 128 rows x 8 k, stride 12 (12g+t distinct mod 32 -> conflict-free frags)
    // W plane: 8 k x 128 cols, stride 136
    __shared__ uint32_t sAhi[2][128 * 12];
    __shared__ uint32_t sAlo[2][128 * 12];
    __shared__ uint32_t sWhi[2][8 * 136];
    __shared__ uint32_t sWlo[2][8 * 136];
    __shared__ float red[4 * 128];

    const int tid = threadIdx.x;
    const int warp = tid >> 5;
    const int lane = tid & 31;
    const int warpM = warp >> 2;
    const int warpN = warp & 3;
    const int g = lane >> 2;
    const int t = lane & 3;
    const int row0 = blockIdx.x * 128;

    // per-thread load coords: A: 1 float4 (row aR, k-quad aC); W: 1 float4 (k-row wR, col-quad wC)
    const int aR = tid >> 1, aC = tid & 1;
    const int wR = tid >> 5, wC = tid & 31;
    const int aRow = row0 + aR;

    float Cr[4][4][4];
#pragma unroll
    for (int mt = 0; mt < 4; mt++)
#pragma unroll
        for (int nt = 0; nt < 4; nt++)
#pragma unroll
            for (int j = 0; j < 4; j++) Cr[mt][nt][j] = 0.f;

#pragma unroll
    for (int s = 0; s < 2; s++) {
        if ((s == 0 && !U1) || (s == 1 && !U2)) continue;
        const float* Ap = (s == 0) ? A1 : A2;
        const float* Wp = (s == 0) ? W1 : W2;

        // prologue: load chunk 0, split, store into buffer 0
        {
            float4 va = make_float4(0.f, 0.f, 0.f, 0.f);
            if (aRow < N) va = ld4(Ap + (size_t)aRow * 128 + aC * 4);
            float4 vw = ld4(Wp + (size_t)wR * 128 + wC * 4);
            uint4 h, l;
            split_tf32(va.x, h.x, l.x); split_tf32(va.y, h.y, l.y);
            split_tf32(va.z, h.z, l.z); split_tf32(va.w, h.w, l.w);
            *reinterpret_cast<uint4*>(&sAhi[0][aR * 12 + aC * 4]) = h;
            *reinterpret_cast<uint4*>(&sAlo[0][aR * 12 + aC * 4]) = l;
            split_tf32(vw.x, h.x, l.x); split_tf32(vw.y, h.y, l.y);
            split_tf32(vw.z, h.z, l.z); split_tf32(vw.w, h.w, l.w);
            *reinterpret_cast<uint4*>(&sWhi[0][wR * 136 + wC * 4]) = h;
            *reinterpret_cast<uint4*>(&sWlo[0][wR * 136 + wC * 4]) = l;
        }

        for (int c = 0; c < 16; c++) {
            __syncthreads();
            const int cur = c & 1;
            const int nxt = cur ^ 1;
            // issue next chunk's global loads early (latency overlapped with mma)
            float4 va = make_float4(0.f, 0.f, 0.f, 0.f), vw;
            bool haveNext = (c + 1 < 16);
            if (haveNext) {
                int k0 = (c + 1) * 8;
                if (aRow < N) va = ld4(Ap + (size_t)aRow * 128 + k0 + aC * 4);
                vw = ld4(Wp + (size_t)(k0 + wR) * 128 + wC * 4);
            }

            // compute on current buffer (one k8 group)
            {
                uint32_t bHi[4][2], bLo[4][2];
#pragma unroll
                for (int nt = 0; nt < 4; nt++) {
                    int n0 = warpN * 32 + nt * 8 + g;
                    bHi[nt][0] = sWhi[cur][t * 136 + n0];
                    bHi[nt][1] = sWhi[cur][(t + 4) * 136 + n0];
                    bLo[nt][0] = sWlo[cur][t * 136 + n0];
                    bLo[nt][1] = sWlo[cur][(t + 4) * 136 + n0];
                }
#pragma unroll
                for (int mt = 0; mt < 4; mt++) {
                    int rb = warpM * 64 + mt * 16 + g;
                    uint32_t aHi[4], aLo[4];
                    aHi[0] = sAhi[cur][rb * 12 + t];
                    aHi[1] = sAhi[cur][(rb + 8) * 12 + t];
                    aHi[2] = sAhi[cur][rb * 12 + t + 4];
                    aHi[3] = sAhi[cur][(rb + 8) * 12 + t + 4];
                    aLo[0] = sAlo[cur][rb * 12 + t];
                    aLo[1] = sAlo[cur][(rb + 8) * 12 + t];
                    aLo[2] = sAlo[cur][rb * 12 + t + 4];
                    aLo[3] = sAlo[cur][(rb + 8) * 12 + t + 4];
#pragma unroll
                    for (int nt = 0; nt < 4; nt++) {
                        mma_tf32(Cr[mt][nt], aHi, bHi[nt]);
                        mma_tf32(Cr[mt][nt], aLo, bHi[nt]);
                        mma_tf32(Cr[mt][nt], aHi, bLo[nt]);
                    }
                }
            }

            // split + store next chunk into the other buffer
            if (haveNext) {
                uint4 h, l;
                split_tf32(va.x, h.x, l.x); split_tf32(va.y, h.y, l.y);
                split_tf32(va.z, h.z, l.z); split_tf32(va.w, h.w, l.w);
                *reinterpret_cast<uint4*>(&sAhi[nxt][aR * 12 + aC * 4]) = h;
                *reinterpret_cast<uint4*>(&sAlo[nxt][aR * 12 + aC * 4]) = l;
                split_tf32(vw.x, h.x, l.x); split_tf32(vw.y, h.y, l.y);
                split_tf32(vw.z, h.z, l.z); split_tf32(vw.w, h.w, l.w);
                *reinterpret_cast<uint4*>(&sWhi[nxt][wR * 136 + wC * 4]) = h;
                *reinterpret_cast<uint4*>(&sWlo[nxt][wR * 136 + wC * 4]) = l;
            }
        }
        __syncthreads();  // drain before next source overwrites buffer 0
    }

    // ---- epilogue ----
    float2 bv[4];
    if constexpr (HASB) {
#pragma unroll
        for (int nt = 0; nt < 4; nt++) bv[nt] = ld2(bias + warpN * 32 + nt * 8 + 2 * t);
    }

#pragma unroll
    for (int mt = 0; mt < 4; mt++) {
        int gr0 = row0 + warpM * 64 + mt * 16 + g;
        int gr1 = gr0 + 8;
        bool v0 = gr0 < N, v1 = gr1 < N;
#pragma unroll
        for (int nt = 0; nt < 4; nt++) {
            int col = warpN * 32 + nt * 8 + 2 * t;
            if constexpr (HASPASS) {
                if (v0) {
                    float2 p = ld2(pass + (size_t)gr0 * 128 + col);
                    Cr[mt][nt][0] += p.x; Cr[mt][nt][1] += p.y;
                }
                if (v1) {
                    float2 p = ld2(pass + (size_t)gr1 * 128 + col);
                    Cr[mt][nt][2] += p.x; Cr[mt][nt][3] += p.y;
                }
            }
            if constexpr (HASB) {
                Cr[mt][nt][0] += bv[nt].x; Cr[mt][nt][1] += bv[nt].y;
                Cr[mt][nt][2] += bv[nt].x; Cr[mt][nt][3] += bv[nt].y;
            }
        }
    }

    if constexpr (EPI == 0 || EPI == 4) {
#pragma unroll
        for (int mt = 0; mt < 4; mt++) {
            int gr0 = row0 + warpM * 64 + mt * 16 + g;
            int gr1 = gr0 + 8;
#pragma unroll
            for (int nt = 0; nt < 4; nt++) {
                int col = warpN * 32 + nt * 8 + 2 * t;
                float2 u0 = make_float2(Cr[mt][nt][0], Cr[mt][nt][1]);
                float2 u1 = make_float2(Cr[mt][nt][2], Cr[mt][nt][3]);
                if constexpr (EPI == 4) {
                    u0.x = fmaxf(u0.x, 0.f); u0.y = fmaxf(u0.y, 0.f);
                    u1.x = fmaxf(u1.x, 0.f); u1.y = fmaxf(u1.y, 0.f);
                }
                if (gr0 < N) st2(out + (size_t)gr0 * 128 + col, u0);
                if (gr1 < N) st2(out + (size_t)gr1 * 128 + col, u1);
            }
        }
    } else {
#pragma unroll
        for (int mt = 0; mt < 4; mt++) {
            float s0 = 0.f, s1 = 0.f;
#pragma unroll
            for (int nt = 0; nt < 4; nt++) {
                s0 += Cr[mt][nt][0] * Cr[mt][nt][0] + Cr[mt][nt][1] * Cr[mt][nt][1];
                s1 += Cr[mt][nt][2] * Cr[mt][nt][2] + Cr[mt][nt][3] * Cr[mt][nt][3];
            }
            s0 += __shfl_xor_sync(0xffffffffu, s0, 1);
            s0 += __shfl_xor_sync(0xffffffffu, s0, 2);
            s1 += __shfl_xor_sync(0xffffffffu, s1, 1);
            s1 += __shfl_xor_sync(0xffffffffu, s1, 2);
            if (t == 0) {
                int lr = warpM * 64 + mt * 16 + g;
                red[warpN * 128 + lr] = s0;
                red[warpN * 128 + lr + 8] = s1;
            }
        }
        __syncthreads();
#pragma unroll
        for (int mt = 0; mt < 4; mt++) {
            int lr0 = warpM * 64 + mt * 16 + g;
            int lr1 = lr0 + 8;
            float q0 = red[lr0] + red[128 + lr0] + red[256 + lr0] + red[384 + lr0];
            float q1 = red[lr1] + red[128 + lr1] + red[256 + lr1] + red[384 + lr1];
            float sc0 = 1.0f / fmaxf(sqrtf(q0), 1e-12f);
            float sc1 = 1.0f / fmaxf(sqrtf(q1), 1e-12f);
            int gr0 = row0 + lr0, gr1 = row0 + lr1;
#pragma unroll
            for (int nt = 0; nt < 4; nt++) {
                int col = warpN * 32 + nt * 8 + 2 * t;
                float2 u0 = make_float2(Cr[mt][nt][0] * sc0, Cr[mt][nt][1] * sc0);
                float2 u1 = make_float2(Cr[mt][nt][2] * sc1, Cr[mt][nt][3] * sc1);
                if constexpr (EPI == 2 || EPI == 3) {
                    if (gr0 < N) {
                        float2 p = ld2(out + (size_t)gr0 * 128 + col);
                        u0.x += p.x; u0.y += p.y;
                    }
                    if (gr1 < N) {
                        float2 p = ld2(out + (size_t)gr1 * 128 + col);
                        u1.x += p.x; u1.y += p.y;
                    }
                    if constexpr (EPI == 3) {
                        u0.x = fmaxf(u0.x, 0.f); u0.y = fmaxf(u0.y, 0.f);
                        u1.x = fmaxf(u1.x, 0.f); u1.y = fmaxf(u1.y, 0.f);
                    }
                }
                if (gr0 < N) st2(out + (size_t)gr0 * 128 + col, u0);
                if (gr1 < N) st2(out + (size_t)gr1 * 128 + col, u1);
            }
        }
    }
}

// ---------------- host orchestration ----------------
extern "C" void kernel_launch(void* const* d_in, const int* in_sizes, int n_in,
                              void* d_out, int out_size) {
    const int* nidP = (const int*)d_in[0];
    const int* nidA = (const int*)d_in[1];
    const int* nidS = (const int*)d_in[2];
    const int* Eptr[6];
    int Ecnt[6];
    for (int r = 0; r < 6; r++) {
        Eptr[r] = (const int*)d_in[3 + r];
        Ecnt[r] = in_sizes[3 + r] / 2;
    }
    const float* embP = (const float*)d_in[9];
    const float* embA = (const float*)d_in[10];
    const float* embS = (const float*)d_in[11];
    const float* Wl = (const float*)d_in[12];
    const float* bl = (const float*)d_in[13];
    const float* Wr = (const float*)d_in[14];
    const float* lng = (const float*)d_in[15];
    const float* lnb = (const float*)d_in[16];
    const float* pw1 = (const float*)d_in[17];
    const float* pb1 = (const float*)d_in[18];
    const float* pw2 = (const float*)d_in[19];
    const float* pb2 = (const float*)d_in[20];
    int NPn = in_sizes[0], NAn = in_sizes[1], NSn = in_sizes[2];

    float *xp, *xa, *xs, *yp, *ya, *ys, *agg, *tmp;
    int *rowptr, *cnt, *cursor, *srcs, *part;
    cudaGetSymbolAddress((void**)&xp, g_xp);
    cudaGetSymbolAddress((void**)&xa, g_xa);
    cudaGetSymbolAddress((void**)&xs, g_xs);
    cudaGetSymbolAddress((void**)&yp, g_yp);
    cudaGetSymbolAddress((void**)&ya, g_ya);
    cudaGetSymbolAddress((void**)&ys, g_ys);
    cudaGetSymbolAddress((void**)&agg, g_agg);
    cudaGetSymbolAddress((void**)&tmp, g_tmp);
    cudaGetSymbolAddress((void**)&rowptr, g_rowptr);
    cudaGetSymbolAddress((void**)&cnt, g_cnt);
    cudaGetSymbolAddress((void**)&cursor, g_cursor);
    cudaGetSymbolAddress((void**)&srcs, g_srcs);
    cudaGetSymbolAddress((void**)&part, g_part);

    // relation meta: type ids: 0=perf,1=artist,2=song
    int Ndst[6] = {NPn, NSn, NSn, NAn, NPn, NAn};
    int dstT[6] = {0, 2, 2, 1, 0, 1};
    int srcT[6] = {1, 0, 1, 0, 2, 2};
    bool pre[6] = {true, false, true, false, true, false};
    // layer-0 pre-transform tmp slice offsets (rows): r0->0, r2->NAn, r4->2*NAn
    size_t tmpoff[6] = {0, 0, (size_t)NAn * DD, 0, (size_t)2 * NAn * DD, 0};
    int roff[6], eoff[6];
    int rsum = 0;
    {
        int o = 0;
        for (int r = 0; r < 6; r++) { roff[r] = o; o += Ndst[r]; }
        rsum = o;
        o = 0;
        for (int r = 0; r < 6; r++) { eoff[r] = o; o += Ecnt[r]; }
    }

    float* X[3] = {xp, xa, xs};
    float* Y[3] = {yp, ya, ys};
    int Nt[3] = {NPn, NAn, NSn};

    // launches 1-3: init features from embeddings
    k_gather<<<(NPn * 32 + 255) / 256, 256>>>(embP, nidP, xp, NPn);
    k_gather<<<(NAn * 32 + 255) / 256, 256>>>(embA, nidA, xa, NAn);
    k_gather<<<(NSn * 32 + 255) / 256, 256>>>(embS, nidS, xs, NSn);

    // launches 4-6: layer-0 pre-transform GEMMs (hoisted so ncu -s 5 captures a GEMM)
    {
        int prerels[3] = {0, 2, 4};
        for (int i = 0; i < 3; i++) {
            int r = prerels[i];
            int st = srcT[r];
            int Ns = Nt[st];
            const float* Wlr = Wl + ((size_t)0 * 6 + r) * 16384;
            k_gemm<true, false, false, false, 0><<<(Ns + 127) / 128, 256>>>(
                X[st], Wlr, nullptr, nullptr, nullptr, nullptr, tmp + tmpoff[r], Ns);
        }
    }

    // bulk-zero CSR counters, then build CSR per relation (layer-invariant)
    k_zero<<<(rsum + 255) / 256, 256>>>(cnt, rsum);
    k_zero<<<(rsum + 255) / 256, 256>>>(cursor, rsum);
    for (int r = 0; r < 6; r++) {
        int Nd = Ndst[r], E = Ecnt[r];
        const int* srcp = Eptr[r];
        const int* dstp = Eptr[r] + E;
        int nb = (Nd + 511) / 512;
        k_count<<<(E + 255) / 256, 256>>>(dstp, E, cnt + roff[r]);
        k_scan1<<<nb, 512>>>(cnt + roff[r], rowptr + roff[r], part, Nd);
        k_scan2<<<1, 512>>>(part, nb);
        k_scan3<<<(Nd + 255) / 256, 256>>>(rowptr + roff[r], part, Nd);
        k_scatter<<<(E + 255) / 256, 256>>>(srcp, dstp, E, rowptr + roff[r], cursor + roff[r],
                                            srcs + eoff[r]);
    }

    int order[6] = {0, 4, 1, 2, 3, 5};

    for (int layer = 0; layer < 3; layer++) {
        bool relu = (layer < 2);
        for (int oi = 0; oi < 6; oi++) {
            int r = order[oi];
            bool isFirst = (oi % 2 == 0);
            int Nd = Ndst[r];
            int st = srcT[r], dt = dstT[r];
            int Ns = Nt[st];
            const float* Wlr = Wl + ((size_t)layer * 6 + r) * 16384;
            const float* Wrr = Wr + ((size_t)layer * 6 + r) * 16384;
            const float* blr = bl + ((size_t)layer * 6 + r) * 128;
            int gb = (Nd + 127) / 128;
            int ab = (Nd * 32 + 255) / 256;
            if (pre[r]) {
                float* tsl = (layer == 0) ? (tmp + tmpoff[r]) : tmp;
                if (layer != 0) {
                    k_gemm<true, false, false, false, 0><<<(Ns + 127) / 128, 256>>>(
                        X[st], Wlr, nullptr, nullptr, nullptr, nullptr, tsl, Ns);
                }
                k_agg<<<ab, 256>>>(tsl, rowptr + roff[r], cnt + roff[r], srcs + eoff[r], agg, Nd);
                if (isFirst)
                    k_gemm<false, true, true, true, 1><<<gb, 256>>>(
                        nullptr, nullptr, X[dt], Wrr, blr, agg, Y[dt], Nd);
                else if (relu)
                    k_gemm<false, true, true, true, 3><<<gb, 256>>>(
                        nullptr, nullptr, X[dt], Wrr, blr, agg, Y[dt], Nd);
                else
                    k_gemm<false, true, true, true, 2><<<gb, 256>>>(
                        nullptr, nullptr, X[dt], Wrr, blr, agg, Y[dt], Nd);
            } else {
                k_agg<<<ab, 256>>>(X[st], rowptr + roff[r], cnt + roff[r], srcs + eoff[r], agg, Nd);
                if (isFirst)
                    k_gemm<true, true, true, false, 1><<<gb, 256>>>(
                        agg, Wlr, X[dt], Wrr, blr, nullptr, Y[dt], Nd);
                else if (relu)
                    k_gemm<true, true, true, false, 3><<<gb, 256>>>(
                        agg, Wlr, X[dt], Wrr, blr, nullptr, Y[dt], Nd);
                else
                    k_gemm<true, true, true, false, 2><<<gb, 256>>>(
                        agg, Wlr, X[dt], Wrr, blr, nullptr, Y[dt], Nd);
            }
        }
        for (int t = 0; t < 3; t++) {
            float* z = X[t];
            X[t] = Y[t];
            Y[t] = z;
        }
    }

    // projection head per type; output order: performance, artist, song
    float* outp = (float*)d_out;
    float* outsec[3] = {outp, outp + (size_t)NPn * 128, outp + (size_t)(NPn + NAn) * 128};
    for (int t = 0; t < 3; t++) {
        int N = Nt[t];
        k_ln<<<(N * 32 + 255) / 256, 256>>>(X[t], lng + t * 128, lnb + t * 128, Y[t], N);
        k_gemm<true, false, true, false, 4><<<(N + 127) / 128, 256>>>(
            Y[t], pw1 + (size_t)t * 16384, nullptr, nullptr, pb1 + t * 128, nullptr, agg, N);
        k_gemm<true, false, true, false, 1><<<(N + 127) / 128, 256>>>(
            agg, pw2 + (size_t)t * 16384, nullptr, nullptr, pb2 + t * 128, nullptr, outsec[t], N);
    }
}

// round 9
// speedup vs baseline: 1.6317x; 1.2824x over previous
#include <cuda_runtime.h>
#include <cuda_bf16.h>
#include <math.h>
#include <stdint.h>

#define DD 128

static const int MAXP = 200000;
static const int MAXA = 30000;
static const int MAXS = 50000;
static const int MAXTMP = 110000;     // 30k (r0) + 30k (r2) + 50k (r4) slices
static const int MAXE_TOT = 2000000;
static const int MAXN_TOT = 560000 + 64;

// ---------------- scratch (static __device__, no allocations) ----------------
__device__ float g_xp[MAXP * DD];
__device__ float g_xa[MAXA * DD];
__device__ float g_xs[MAXS * DD];
__device__ float g_yp[MAXP * DD];
__device__ float g_ya[MAXA * DD];
__device__ float g_ys[MAXS * DD];
__device__ float g_agg[MAXP * DD];
__device__ float g_tmp[MAXTMP * DD];
__device__ int g_rowptr[MAXN_TOT];
__device__ int g_cnt[MAXN_TOT];
__device__ int g_cursor[MAXN_TOT];
__device__ int g_srcs[MAXE_TOT];
__device__ int g_part[1024];

// ---------------- small helpers ----------------
__device__ __forceinline__ float4 ld4(const float* p) { return *reinterpret_cast<const float4*>(p); }
__device__ __forceinline__ void st4(float* p, float4 v) { *reinterpret_cast<float4*>(p) = v; }
__device__ __forceinline__ float2 ld2(const float* p) { return *reinterpret_cast<const float2*>(p); }
__device__ __forceinline__ void st2(float* p, float2 v) { *reinterpret_cast<float2*>(p) = v; }
__device__ __forceinline__ float4 f4add(float4 a, float4 b) {
    return make_float4(a.x + b.x, a.y + b.y, a.z + b.z, a.w + b.w);
}

// pack two floats into bf16x2: lower 16 bits = lo_elem (smaller k), upper = hi_elem
__device__ __forceinline__ uint32_t pack_bf16x2(float lo_elem, float hi_elem) {
    uint32_t d;
    asm("cvt.rn.bf16x2.f32 %0, %1, %2;" : "=r"(d) : "f"(hi_elem), "f"(lo_elem));
    return d;
}

// bf16 split: a = hi + lo (hi, lo each bf16-representable to ~2^-17 total)
__device__ __forceinline__ void split_bf16(float a, float& hi, float& lo) {
    __nv_bfloat16 h = __float2bfloat16_rn(a);
    hi = __bfloat162float(h);
    lo = a - hi;
}

__device__ __forceinline__ void mma_bf16(float* c, const uint32_t* a, const uint32_t* b) {
    asm volatile(
        "mma.sync.aligned.m16n8k16.row.col.f32.bf16.bf16.f32 "
        "{%0,%1,%2,%3}, {%4,%5,%6,%7}, {%8,%9}, {%0,%1,%2,%3};"
        : "+f"(c[0]), "+f"(c[1]), "+f"(c[2]), "+f"(c[3])
        : "r"(a[0]), "r"(a[1]), "r"(a[2]), "r"(a[3]), "r"(b[0]), "r"(b[1]));
}

// ---------------- utility kernels ----------------
__global__ void k_zero(int* p, int n) {
    int i = blockIdx.x * blockDim.x + threadIdx.x;
    if (i < n) p[i] = 0;
}

__global__ void k_gather(const float* __restrict__ emb, const int* __restrict__ nid,
                         float* __restrict__ x, int n) {
    int i = blockIdx.x * blockDim.x + threadIdx.x;
    if (i < n * 32) {
        int r = i >> 5, c = i & 31;
        st4(x + (size_t)r * DD + c * 4, ld4(emb + (size_t)nid[r] * DD + c * 4));
    }
}

__global__ void k_count(const int* __restrict__ dst, int E, int* cnt) {
    int e = blockIdx.x * blockDim.x + threadIdx.x;
    if (e < E) atomicAdd(&cnt[dst[e]], 1);
}

__global__ void k_scan1(const int* __restrict__ cnt, int* __restrict__ rowptr,
                        int* __restrict__ part, int N) {
    __shared__ int s[512];
    int tid = threadIdx.x;
    int i = blockIdx.x * 512 + tid;
    int v = (i < N) ? cnt[i] : 0;
    s[tid] = v;
    __syncthreads();
    for (int off = 1; off < 512; off <<= 1) {
        int t = (tid >= off) ? s[tid - off] : 0;
        __syncthreads();
        s[tid] += t;
        __syncthreads();
    }
    if (i < N) rowptr[i] = s[tid] - v;
    if (tid == 511) part[blockIdx.x] = s[511];
}

__global__ void k_scan2(int* part, int n) {
    __shared__ int s[512];
    int tid = threadIdx.x;
    int v = (tid < n) ? part[tid] : 0;
    s[tid] = v;
    __syncthreads();
    for (int off = 1; off < 512; off <<= 1) {
        int t = (tid >= off) ? s[tid - off] : 0;
        __syncthreads();
        s[tid] += t;
        __syncthreads();
    }
    if (tid < n) part[tid] = s[tid] - v;
}

__global__ void k_scan3(int* rowptr, const int* __restrict__ part, int N) {
    int i = blockIdx.x * blockDim.x + threadIdx.x;
    if (i < N) rowptr[i] += part[i >> 9];
}

__global__ void k_scatter(const int* __restrict__ src, const int* __restrict__ dst, int E,
                          const int* __restrict__ rowptr, int* __restrict__ cursor,
                          int* __restrict__ out) {
    int e = blockIdx.x * blockDim.x + threadIdx.x;
    if (e < E) {
        int d = dst[e];
        int pos = rowptr[d] + atomicAdd(&cursor[d], 1);
        out[pos] = src[e];
    }
}

// segment-mean gather: one warp per destination row
__global__ void k_agg(const float* __restrict__ feat, const int* __restrict__ rowptr,
                      const int* __restrict__ cnt, const int* __restrict__ srcs,
                      float* __restrict__ out, int N) {
    int warp = (blockIdx.x * blockDim.x + threadIdx.x) >> 5;
    if (warp >= N) return;
    int lane = threadIdx.x & 31;
    int beg = rowptr[warp], n = cnt[warp];
    float4 acc = make_float4(0.f, 0.f, 0.f, 0.f);
    int i = 0;
    for (; i + 4 <= n; i += 4) {
        int s0 = srcs[beg + i], s1 = srcs[beg + i + 1];
        int s2 = srcs[beg + i + 2], s3 = srcs[beg + i + 3];
        float4 v0 = ld4(feat + (size_t)s0 * DD + lane * 4);
        float4 v1 = ld4(feat + (size_t)s1 * DD + lane * 4);
        float4 v2 = ld4(feat + (size_t)s2 * DD + lane * 4);
        float4 v3 = ld4(feat + (size_t)s3 * DD + lane * 4);
        acc = f4add(acc, f4add(f4add(v0, v1), f4add(v2, v3)));
    }
    for (; i < n; i++) {
        int s = srcs[beg + i];
        acc = f4add(acc, ld4(feat + (size_t)s * DD + lane * 4));
    }
    float inv = 1.0f / (float)max(n, 1);
    acc.x *= inv; acc.y *= inv; acc.z *= inv; acc.w *= inv;
    st4(out + (size_t)warp * DD + lane * 4, acc);
}

// layernorm: one warp per row
__global__ void k_ln(const float* __restrict__ x, const float* __restrict__ g,
                     const float* __restrict__ b, float* __restrict__ y, int N) {
    int warp = (blockIdx.x * blockDim.x + threadIdx.x) >> 5;
    if (warp >= N) return;
    int lane = threadIdx.x & 31;
    float4 v = ld4(x + (size_t)warp * DD + lane * 4);
    float s = v.x + v.y + v.z + v.w;
#pragma unroll
    for (int m = 16; m > 0; m >>= 1) s += __shfl_xor_sync(0xffffffffu, s, m);
    float mu = s * (1.0f / 128.0f);
    float4 d = make_float4(v.x - mu, v.y - mu, v.z - mu, v.w - mu);
    float ss = d.x * d.x + d.y * d.y + d.z * d.z + d.w * d.w;
#pragma unroll
    for (int m = 16; m > 0; m >>= 1) ss += __shfl_xor_sync(0xffffffffu, ss, m);
    float sc = rsqrtf(ss * (1.0f / 128.0f) + 1e-5f);
    float4 gv = ld4(g + lane * 4), bv = ld4(b + lane * 4);
    float4 o = make_float4(d.x * sc * gv.x + bv.x, d.y * sc * gv.y + bv.y,
                           d.z * sc * gv.z + bv.z, d.w * sc * gv.w + bv.w);
    st4(y + (size_t)warp * DD + lane * 4, o);
}

// ---------------- tensor-core fused GEMM (3xBF16 m16n8k16, double-buffered) -------------
// h = (U1 ? A1@W1 : 0) + (U2 ? A2@W2 : 0) + (HASPASS ? pass : 0) + (HASB ? bias : 0)
// EPI: 0 = store; 1 = l2norm store; 2 = l2norm add; 3 = l2norm add + relu; 4 = relu store
// Block tile 128x128, 8 warps (2m x 4n), warp tile 64x32, K chunk 16 (1 mma-k per chunk).
// smem planes hold bf16x2-packed k-pairs: A[row][pair p] (p=k/2, 8 pairs), W[pair p][col].
template <bool U1, bool U2, bool HASB, bool HASPASS, int EPI>
__global__ void __launch_bounds__(256, 2)
k_gemm(const float* __restrict__ A1, const float* __restrict__ W1,
       const float* __restrict__ A2, const float* __restrict__ W2,
       const float* __restrict__ bias, const float* __restrict__ pass,
       float* __restrict__ out, int N) {
    // A plane: 128 rows x 8 pairs, stride 12 (12g+t distinct mod 32 -> conflict-free)
    // W plane: 8 pair-rows x 128 cols, stride 136
    __shared__ uint32_t sAhi[2][128 * 12];
    __shared__ uint32_t sAlo[2][128 * 12];
    __shared__ uint32_t sWhi[2][8 * 136];
    __shared__ uint32_t sWlo[2][8 * 136];
    __shared__ float red[4 * 128];

    const int tid = threadIdx.x;
    const int warp = tid >> 5;
    const int lane = tid & 31;
    const int warpM = warp >> 2;
    const int warpN = warp & 3;
    const int g = lane >> 2;
    const int t = lane & 3;
    const int row0 = blockIdx.x * 128;

    // per-thread load coords:
    // A: row aR = tid>>1, k-half aH = tid&1 (8 k values = 2 float4 -> 4 packed pairs)
    // W: pair-row wP = tid>>5 (k = 2wP, 2wP+1), col quad wC = tid&31 (4 cols -> 4 packed)
    const int aR = tid >> 1, aH = tid & 1;
    const int wP = tid >> 5, wC = tid & 31;
    const int aRow = row0 + aR;

    float Cr[4][4][4];
#pragma unroll
    for (int mt = 0; mt < 4; mt++)
#pragma unroll
        for (int nt = 0; nt < 4; nt++)
#pragma unroll
            for (int j = 0; j < 4; j++) Cr[mt][nt][j] = 0.f;

#pragma unroll
    for (int s = 0; s < 2; s++) {
        if ((s == 0 && !U1) || (s == 1 && !U2)) continue;
        const float* Ap = (s == 0) ? A1 : A2;
        const float* Wp = (s == 0) ? W1 : W2;

        // staging: split 8 A values + 8 W values -> packed hi/lo pairs, store to buffer
        auto stage = [&](int buf, int k0, float4 va0, float4 va1, float4 vw0, float4 vw1) {
            // A: va0 = A[row][k0+8aH .. +3], va1 = +4..+7  (4 consecutive pairs)
            float h0, l0, h1, l1;
            uint4 ph, pl;
            split_bf16(va0.x, h0, l0); split_bf16(va0.y, h1, l1);
            ph.x = pack_bf16x2(h0, h1); pl.x = pack_bf16x2(l0, l1);
            split_bf16(va0.z, h0, l0); split_bf16(va0.w, h1, l1);
            ph.y = pack_bf16x2(h0, h1); pl.y = pack_bf16x2(l0, l1);
            split_bf16(va1.x, h0, l0); split_bf16(va1.y, h1, l1);
            ph.z = pack_bf16x2(h0, h1); pl.z = pack_bf16x2(l0, l1);
            split_bf16(va1.z, h0, l0); split_bf16(va1.w, h1, l1);
            ph.w = pack_bf16x2(h0, h1); pl.w = pack_bf16x2(l0, l1);
            *reinterpret_cast<uint4*>(&sAhi[buf][aR * 12 + aH * 4]) = ph;
            *reinterpret_cast<uint4*>(&sAlo[buf][aR * 12 + aH * 4]) = pl;
            // W: vw0 = W[k even][n..n+3], vw1 = W[k odd][n..n+3]; pack along k
            float he, le, ho, lo;
            split_bf16(vw0.x, he, le); split_bf16(vw1.x, ho, lo);
            ph.x = pack_bf16x2(he, ho); pl.x = pack_bf16x2(le, lo);
            split_bf16(vw0.y, he, le); split_bf16(vw1.y, ho, lo);
            ph.y = pack_bf16x2(he, ho); pl.y = pack_bf16x2(le, lo);
            split_bf16(vw0.z, he, le); split_bf16(vw1.z, ho, lo);
            ph.z = pack_bf16x2(he, ho); pl.z = pack_bf16x2(le, lo);
            split_bf16(vw0.w, he, le); split_bf16(vw1.w, ho, lo);
            ph.w = pack_bf16x2(he, ho); pl.w = pack_bf16x2(le, lo);
            *reinterpret_cast<uint4*>(&sWhi[buf][wP * 136 + wC * 4]) = ph;
            *reinterpret_cast<uint4*>(&sWlo[buf][wP * 136 + wC * 4]) = pl;
        };
        auto loadg = [&](int k0, float4& va0, float4& va1, float4& vw0, float4& vw1) {
            va0 = make_float4(0.f, 0.f, 0.f, 0.f);
            va1 = make_float4(0.f, 0.f, 0.f, 0.f);
            if (aRow < N) {
                va0 = ld4(Ap + (size_t)aRow * 128 + k0 + aH * 8);
                va1 = ld4(Ap + (size_t)aRow * 128 + k0 + aH * 8 + 4);
            }
            vw0 = ld4(Wp + (size_t)(k0 + 2 * wP) * 128 + wC * 4);
            vw1 = ld4(Wp + (size_t)(k0 + 2 * wP + 1) * 128 + wC * 4);
        };

        // prologue: chunk 0 into buffer 0
        {
            float4 va0, va1, vw0, vw1;
            loadg(0, va0, va1, vw0, vw1);
            stage(0, 0, va0, va1, vw0, vw1);
        }

        for (int c = 0; c < 8; c++) {
            __syncthreads();
            const int cur = c & 1;
            const int nxt = cur ^ 1;
            float4 va0, va1, vw0, vw1;
            bool haveNext = (c + 1 < 8);
            if (haveNext) loadg((c + 1) * 16, va0, va1, vw0, vw1);

            // compute on current buffer (one k16 step)
            {
                uint32_t bHi[4][2], bLo[4][2];
#pragma unroll
                for (int nt = 0; nt < 4; nt++) {
                    int n0 = warpN * 32 + nt * 8 + g;
                    bHi[nt][0] = sWhi[cur][t * 136 + n0];
                    bHi[nt][1] = sWhi[cur][(t + 4) * 136 + n0];
                    bLo[nt][0] = sWlo[cur][t * 136 + n0];
                    bLo[nt][1] = sWlo[cur][(t + 4) * 136 + n0];
                }
#pragma unroll
                for (int mt = 0; mt < 4; mt++) {
                    int rb = warpM * 64 + mt * 16 + g;
                    uint32_t aHi[4], aLo[4];
                    aHi[0] = sAhi[cur][rb * 12 + t];
                    aHi[1] = sAhi[cur][(rb + 8) * 12 + t];
                    aHi[2] = sAhi[cur][rb * 12 + t + 4];
                    aHi[3] = sAhi[cur][(rb + 8) * 12 + t + 4];
                    aLo[0] = sAlo[cur][rb * 12 + t];
                    aLo[1] = sAlo[cur][(rb + 8) * 12 + t];
                    aLo[2] = sAlo[cur][rb * 12 + t + 4];
                    aLo[3] = sAlo[cur][(rb + 8) * 12 + t + 4];
#pragma unroll
                    for (int nt = 0; nt < 4; nt++) {
                        mma_bf16(Cr[mt][nt], aHi, bHi[nt]);
                        mma_bf16(Cr[mt][nt], aLo, bHi[nt]);
                        mma_bf16(Cr[mt][nt], aHi, bLo[nt]);
                    }
                }
            }

            if (haveNext) stage(nxt, (c + 1) * 16, va0, va1, vw0, vw1);
        }
        __syncthreads();  // drain before next source overwrites buffer 0
    }

    // ---- epilogue ----
    float2 bv[4];
    if constexpr (HASB) {
#pragma unroll
        for (int nt = 0; nt < 4; nt++) bv[nt] = ld2(bias + warpN * 32 + nt * 8 + 2 * t);
    }

#pragma unroll
    for (int mt = 0; mt < 4; mt++) {
        int gr0 = row0 + warpM * 64 + mt * 16 + g;
        int gr1 = gr0 + 8;
        bool v0 = gr0 < N, v1 = gr1 < N;
#pragma unroll
        for (int nt = 0; nt < 4; nt++) {
            int col = warpN * 32 + nt * 8 + 2 * t;
            if constexpr (HASPASS) {
                if (v0) {
                    float2 p = ld2(pass + (size_t)gr0 * 128 + col);
                    Cr[mt][nt][0] += p.x; Cr[mt][nt][1] += p.y;
                }
                if (v1) {
                    float2 p = ld2(pass + (size_t)gr1 * 128 + col);
                    Cr[mt][nt][2] += p.x; Cr[mt][nt][3] += p.y;
                }
            }
            if constexpr (HASB) {
                Cr[mt][nt][0] += bv[nt].x; Cr[mt][nt][1] += bv[nt].y;
                Cr[mt][nt][2] += bv[nt].x; Cr[mt][nt][3] += bv[nt].y;
            }
        }
    }

    if constexpr (EPI == 0 || EPI == 4) {
#pragma unroll
        for (int mt = 0; mt < 4; mt++) {
            int gr0 = row0 + warpM * 64 + mt * 16 + g;
            int gr1 = gr0 + 8;
#pragma unroll
            for (int nt = 0; nt < 4; nt++) {
                int col = warpN * 32 + nt * 8 + 2 * t;
                float2 u0 = make_float2(Cr[mt][nt][0], Cr[mt][nt][1]);
                float2 u1 = make_float2(Cr[mt][nt][2], Cr[mt][nt][3]);
                if constexpr (EPI == 4) {
                    u0.x = fmaxf(u0.x, 0.f); u0.y = fmaxf(u0.y, 0.f);
                    u1.x = fmaxf(u1.x, 0.f); u1.y = fmaxf(u1.y, 0.f);
                }
                if (gr0 < N) st2(out + (size_t)gr0 * 128 + col, u0);
                if (gr1 < N) st2(out + (size_t)gr1 * 128 + col, u1);
            }
        }
    } else {
#pragma unroll
        for (int mt = 0; mt < 4; mt++) {
            float s0 = 0.f, s1 = 0.f;
#pragma unroll
            for (int nt = 0; nt < 4; nt++) {
                s0 += Cr[mt][nt][0] * Cr[mt][nt][0] + Cr[mt][nt][1] * Cr[mt][nt][1];
                s1 += Cr[mt][nt][2] * Cr[mt][nt][2] + Cr[mt][nt][3] * Cr[mt][nt][3];
            }
            s0 += __shfl_xor_sync(0xffffffffu, s0, 1);
            s0 += __shfl_xor_sync(0xffffffffu, s0, 2);
            s1 += __shfl_xor_sync(0xffffffffu, s1, 1);
            s1 += __shfl_xor_sync(0xffffffffu, s1, 2);
            if (t == 0) {
                int lr = warpM * 64 + mt * 16 + g;
                red[warpN * 128 + lr] = s0;
                red[warpN * 128 + lr + 8] = s1;
            }
        }
        __syncthreads();
#pragma unroll
        for (int mt = 0; mt < 4; mt++) {
            int lr0 = warpM * 64 + mt * 16 + g;
            int lr1 = lr0 + 8;
            float q0 = red[lr0] + red[128 + lr0] + red[256 + lr0] + red[384 + lr0];
            float q1 = red[lr1] + red[128 + lr1] + red[256 + lr1] + red[384 + lr1];
            float sc0 = 1.0f / fmaxf(sqrtf(q0), 1e-12f);
            float sc1 = 1.0f / fmaxf(sqrtf(q1), 1e-12f);
            int gr0 = row0 + lr0, gr1 = row0 + lr1;
#pragma unroll
            for (int nt = 0; nt < 4; nt++) {
                int col = warpN * 32 + nt * 8 + 2 * t;
                float2 u0 = make_float2(Cr[mt][nt][0] * sc0, Cr[mt][nt][1] * sc0);
                float2 u1 = make_float2(Cr[mt][nt][2] * sc1, Cr[mt][nt][3] * sc1);
                if constexpr (EPI == 2 || EPI == 3) {
                    if (gr0 < N) {
                        float2 p = ld2(out + (size_t)gr0 * 128 + col);
                        u0.x += p.x; u0.y += p.y;
                    }
                    if (gr1 < N) {
                        float2 p = ld2(out + (size_t)gr1 * 128 + col);
                        u1.x += p.x; u1.y += p.y;
                    }
                    if constexpr (EPI == 3) {
                        u0.x = fmaxf(u0.x, 0.f); u0.y = fmaxf(u0.y, 0.f);
                        u1.x = fmaxf(u1.x, 0.f); u1.y = fmaxf(u1.y, 0.f);
                    }
                }
                if (gr0 < N) st2(out + (size_t)gr0 * 128 + col, u0);
                if (gr1 < N) st2(out + (size_t)gr1 * 128 + col, u1);
            }
        }
    }
}

// ---------------- host orchestration ----------------
extern "C" void kernel_launch(void* const* d_in, const int* in_sizes, int n_in,
                              void* d_out, int out_size) {
    const int* nidP = (const int*)d_in[0];
    const int* nidA = (const int*)d_in[1];
    const int* nidS = (const int*)d_in[2];
    const int* Eptr[6];
    int Ecnt[6];
    for (int r = 0; r < 6; r++) {
        Eptr[r] = (const int*)d_in[3 + r];
        Ecnt[r] = in_sizes[3 + r] / 2;
    }
    const float* embP = (const float*)d_in[9];
    const float* embA = (const float*)d_in[10];
    const float* embS = (const float*)d_in[11];
    const float* Wl = (const float*)d_in[12];
    const float* bl = (const float*)d_in[13];
    const float* Wr = (const float*)d_in[14];
    const float* lng = (const float*)d_in[15];
    const float* lnb = (const float*)d_in[16];
    const float* pw1 = (const float*)d_in[17];
    const float* pb1 = (const float*)d_in[18];
    const float* pw2 = (const float*)d_in[19];
    const float* pb2 = (const float*)d_in[20];
    int NPn = in_sizes[0], NAn = in_sizes[1], NSn = in_sizes[2];

    float *xp, *xa, *xs, *yp, *ya, *ys, *agg, *tmp;
    int *rowptr, *cnt, *cursor, *srcs, *part;
    cudaGetSymbolAddress((void**)&xp, g_xp);
    cudaGetSymbolAddress((void**)&xa, g_xa);
    cudaGetSymbolAddress((void**)&xs, g_xs);
    cudaGetSymbolAddress((void**)&yp, g_yp);
    cudaGetSymbolAddress((void**)&ya, g_ya);
    cudaGetSymbolAddress((void**)&ys, g_ys);
    cudaGetSymbolAddress((void**)&agg, g_agg);
    cudaGetSymbolAddress((void**)&tmp, g_tmp);
    cudaGetSymbolAddress((void**)&rowptr, g_rowptr);
    cudaGetSymbolAddress((void**)&cnt, g_cnt);
    cudaGetSymbolAddress((void**)&cursor, g_cursor);
    cudaGetSymbolAddress((void**)&srcs, g_srcs);
    cudaGetSymbolAddress((void**)&part, g_part);

    // relation meta: type ids: 0=perf,1=artist,2=song
    int Ndst[6] = {NPn, NSn, NSn, NAn, NPn, NAn};
    int dstT[6] = {0, 2, 2, 1, 0, 1};
    int srcT[6] = {1, 0, 1, 0, 2, 2};
    bool pre[6] = {true, false, true, false, true, false};
    // layer-0 pre-transform tmp slice offsets (rows): r0->0, r2->NAn, r4->2*NAn
    size_t tmpoff[6] = {0, 0, (size_t)NAn * DD, 0, (size_t)2 * NAn * DD, 0};
    int roff[6], eoff[6];
    int rsum = 0;
    {
        int o = 0;
        for (int r = 0; r < 6; r++) { roff[r] = o; o += Ndst[r]; }
        rsum = o;
        o = 0;
        for (int r = 0; r < 6; r++) { eoff[r] = o; o += Ecnt[r]; }
    }

    float* X[3] = {xp, xa, xs};
    float* Y[3] = {yp, ya, ys};
    int Nt[3] = {NPn, NAn, NSn};

    // launches 1-3: init features from embeddings
    k_gather<<<(NPn * 32 + 255) / 256, 256>>>(embP, nidP, xp, NPn);
    k_gather<<<(NAn * 32 + 255) / 256, 256>>>(embA, nidA, xa, NAn);
    k_gather<<<(NSn * 32 + 255) / 256, 256>>>(embS, nidS, xs, NSn);

    // launches 4-6: layer-0 pre-transform GEMMs (hoisted so ncu -s 5 captures a GEMM)
    {
        int prerels[3] = {0, 2, 4};
        for (int i = 0; i < 3; i++) {
            int r = prerels[i];
            int st = srcT[r];
            int Ns = Nt[st];
            const float* Wlr = Wl + ((size_t)0 * 6 + r) * 16384;
            k_gemm<true, false, false, false, 0><<<(Ns + 127) / 128, 256>>>(
                X[st], Wlr, nullptr, nullptr, nullptr, nullptr, tmp + tmpoff[r], Ns);
        }
    }

    // bulk-zero CSR counters, then build CSR per relation (layer-invariant)
    k_zero<<<(rsum + 255) / 256, 256>>>(cnt, rsum);
    k_zero<<<(rsum + 255) / 256, 256>>>(cursor, rsum);
    for (int r = 0; r < 6; r++) {
        int Nd = Ndst[r], E = Ecnt[r];
        const int* srcp = Eptr[r];
        const int* dstp = Eptr[r] + E;
        int nb = (Nd + 511) / 512;
        k_count<<<(E + 255) / 256, 256>>>(dstp, E, cnt + roff[r]);
        k_scan1<<<nb, 512>>>(cnt + roff[r], rowptr + roff[r], part, Nd);
        k_scan2<<<1, 512>>>(part, nb);
        k_scan3<<<(Nd + 255) / 256, 256>>>(rowptr + roff[r], part, Nd);
        k_scatter<<<(E + 255) / 256, 256>>>(srcp, dstp, E, rowptr + roff[r], cursor + roff[r],
                                            srcs + eoff[r]);
    }

    int order[6] = {0, 4, 1, 2, 3, 5};

    for (int layer = 0; layer < 3; layer++) {
        bool relu = (layer < 2);
        for (int oi = 0; oi < 6; oi++) {
            int r = order[oi];
            bool isFirst = (oi % 2 == 0);
            int Nd = Ndst[r];
            int st = srcT[r], dt = dstT[r];
            int Ns = Nt[st];
            const float* Wlr = Wl + ((size_t)layer * 6 + r) * 16384;
            const float* Wrr = Wr + ((size_t)layer * 6 + r) * 16384;
            const float* blr = bl + ((size_t)layer * 6 + r) * 128;
            int gb = (Nd + 127) / 128;
            int ab = (Nd * 32 + 255) / 256;
            if (pre[r]) {
                float* tsl = (layer == 0) ? (tmp + tmpoff[r]) : tmp;
                if (layer != 0) {
                    k_gemm<true, false, false, false, 0><<<(Ns + 127) / 128, 256>>>(
                        X[st], Wlr, nullptr, nullptr, nullptr, nullptr, tsl, Ns);
                }
                k_agg<<<ab, 256>>>(tsl, rowptr + roff[r], cnt + roff[r], srcs + eoff[r], agg, Nd);
                if (isFirst)
                    k_gemm<false, true, true, true, 1><<<gb, 256>>>(
                        nullptr, nullptr, X[dt], Wrr, blr, agg, Y[dt], Nd);
                else if (relu)
                    k_gemm<false, true, true, true, 3><<<gb, 256>>>(
                        nullptr, nullptr, X[dt], Wrr, blr, agg, Y[dt], Nd);
                else
                    k_gemm<false, true, true, true, 2><<<gb, 256>>>(
                        nullptr, nullptr, X[dt], Wrr, blr, agg, Y[dt], Nd);
            } else {
                k_agg<<<ab, 256>>>(X[st], rowptr + roff[r], cnt + roff[r], srcs + eoff[r], agg, Nd);
                if (isFirst)
                    k_gemm<true, true, true, false, 1><<<gb, 256>>>(
                        agg, Wlr, X[dt], Wrr, blr, nullptr, Y[dt], Nd);
                else if (relu)
                    k_gemm<true, true, true, false, 3><<<gb, 256>>>(
                        agg, Wlr, X[dt], Wrr, blr, nullptr, Y[dt], Nd);
                else
                    k_gemm<true, true, true, false, 2><<<gb, 256>>>(
                        agg, Wlr, X[dt], Wrr, blr, nullptr, Y[dt], Nd);
            }
        }
        for (int t = 0; t < 3; t++) {
            float* z = X[t];
            X[t] = Y[t];
            Y[t] = z;
        }
    }

    // projection head per type; output order: performance, artist, song
    float* outp = (float*)d_out;
    float* outsec[3] = {outp, outp + (size_t)NPn * 128, outp + (size_t)(NPn + NAn) * 128};
    for (int t = 0; t < 3; t++) {
        int N = Nt[t];
        k_ln<<<(N * 32 + 255) / 256, 256>>>(X[t], lng + t * 128, lnb + t * 128, Y[t], N);
        k_gemm<true, false, true, false, 4><<<(N + 127) / 128, 256>>>(
            Y[t], pw1 + (size_t)t * 16384, nullptr, nullptr, pb1 + t * 128, nullptr, agg, N);
        k_gemm<true, false, true, false, 1><<<(N + 127) / 128, 256>>>(
            agg, pw2 + (size_t)t * 16384, nullptr, nullptr, pb2 + t * 128, nullptr, outsec[t], N);
    }
}